// round 2
// baseline (speedup 1.0000x reference)
#include <cuda_runtime.h>
#include <cuda_bf16.h>
#include <math.h>

// Problem constants
#define NN 50000
#define EE 800000
#define ET 850000   // EE + NN self loops
#define F1 256      // HEADS*HID
#define HH 4
#define CC 64
#define OC 64

// ---------------- device scratch (no allocations allowed) ----------------
__device__ float  g_h1[(size_t)NN * F1];   // x @ W1
__device__ float  g_x1[(size_t)NN * F1];   // layer-1 output (post relu+bias)
__device__ float  g_h2[(size_t)NN * OC];   // x1 @ W2
__device__ float  g_as1[NN * HH];
__device__ float  g_ad1[NN * HH];
__device__ float  g_as2[NN];
__device__ float  g_ad2[NN];
__device__ float4 g_alpha1[ET];            // per sorted-edge leaky alphas, 4 heads
__device__ float  g_alpha2[ET];
__device__ int    g_deg[NN];
__device__ int    g_off[NN + 1];
__device__ int    g_pos[NN];
__device__ int    g_srcs[ET];
__device__ int    g_dsts[ET];
__device__ int    g_is64;                  // 1 if edge_index is int64, 0 if int32

// ---------------- helpers ----------------
__device__ __forceinline__ float warpRedSum(float v) {
#pragma unroll
    for (int o = 16; o; o >>= 1) v += __shfl_down_sync(0xffffffffu, v, o);
    return v;
}
__device__ __forceinline__ float warpRedMax(float v) {
#pragma unroll
    for (int o = 16; o; o >>= 1) v = fmaxf(v, __shfl_down_sync(0xffffffffu, v, o));
    return v;
}
__device__ __forceinline__ float lrelu(float x) { return x > 0.f ? x : 0.2f * x; }

__device__ __forceinline__ int load_edge(const void* eiv, int idx) {
    if (g_is64) return (int)((const long long*)eiv)[idx];
    return ((const int*)eiv)[idx];
}

// ---------------- dtype sniff ----------------
__global__ void detect_kernel(const void* eiv) {
    if (threadIdx.x == 0) {
        const long long* p = (const long long*)eiv;
        int ok = 1;
        for (int i = 0; i < 256; i++) {
            long long v = p[i];
            if (v < 0 || v >= NN) { ok = 0; break; }
        }
        g_is64 = ok;
    }
}

// ---------------- CSR build ----------------
__global__ void zero_deg_kernel() {
    int i = blockIdx.x * blockDim.x + threadIdx.x;
    if (i < NN) g_deg[i] = 0;
}

__global__ void count_kernel(const void* __restrict__ eiv) {
    int e = blockIdx.x * blockDim.x + threadIdx.x;
    if (e >= ET) return;
    int dst = (e < EE) ? load_edge(eiv, EE + e) : (e - EE);
    atomicAdd(&g_deg[dst], 1);
}

__global__ void scan_kernel() {
    const int T = 1024;
    int tid = threadIdx.x;
    int lane = tid & 31, wid = tid >> 5;
    const int per = (NN + T - 1) / T;
    int start = tid * per;
    int end = min(start + per, NN);
    int s = 0;
    for (int i = start; i < end; i++) s += g_deg[i];
    int v = s;
#pragma unroll
    for (int o = 1; o < 32; o <<= 1) {
        int u = __shfl_up_sync(0xffffffffu, v, o);
        if (lane >= o) v += u;
    }
    __shared__ int ws[32];
    if (lane == 31) ws[wid] = v;
    __syncthreads();
    if (wid == 0) {
        int w = ws[lane];
#pragma unroll
        for (int o = 1; o < 32; o <<= 1) {
            int u = __shfl_up_sync(0xffffffffu, w, o);
            if (lane >= o) w += u;
        }
        ws[lane] = w;
    }
    __syncthreads();
    int excl = v - s + (wid > 0 ? ws[wid - 1] : 0);
    int run = excl;
    for (int i = start; i < end; i++) {
        g_off[i] = run;
        g_pos[i] = run;
        run += g_deg[i];
    }
    if (tid == T - 1) g_off[NN] = run;
}

__global__ void fill_kernel(const void* __restrict__ eiv) {
    int e = blockIdx.x * blockDim.x + threadIdx.x;
    if (e >= ET) return;
    int src, dst;
    if (e < EE) { src = load_edge(eiv, e); dst = load_edge(eiv, EE + e); }
    else        { src = dst = e - EE; }
    int p = atomicAdd(&g_pos[dst], 1);
    g_srcs[p] = src;
    g_dsts[p] = dst;
}

// ---------------- SGEMM (A:MxK row-major, B:KxN row-major, C:MxN) ----------------
template <int BM, int BN, int BK, int TM, int TN>
__global__ __launch_bounds__(256)
void sgemm_kernel(const float* __restrict__ A, const float* __restrict__ B,
                  float* __restrict__ C, int M, int Ncol, int K) {
    __shared__ float As[BK][BM];
    __shared__ float Bs[BK][BN];
    const int TX = BN / TN;
    const int tid = threadIdx.x;
    const int tx = tid % TX;
    const int ty = tid / TX;
    const int rowBase = blockIdx.y * BM;
    const int colBase = blockIdx.x * BN;

    float acc[TM][TN];
#pragma unroll
    for (int i = 0; i < TM; i++)
#pragma unroll
        for (int j = 0; j < TN; j++) acc[i][j] = 0.f;

    const int A4 = (BM * BK) / (256 * 4);
    const int B4 = (BK * BN) / (256 * 4);
    const int ac4 = BK / 4;
    const int bc4 = BN / 4;

    for (int k0 = 0; k0 < K; k0 += BK) {
#pragma unroll
        for (int t = 0; t < A4; t++) {
            int idx = t * 256 + tid;
            int r = idx / ac4;
            int c4 = idx % ac4;
            int gr = rowBase + r;
            float4 v = make_float4(0.f, 0.f, 0.f, 0.f);
            if (gr < M) v = *(const float4*)(A + (size_t)gr * K + k0 + c4 * 4);
            As[c4 * 4 + 0][r] = v.x;
            As[c4 * 4 + 1][r] = v.y;
            As[c4 * 4 + 2][r] = v.z;
            As[c4 * 4 + 3][r] = v.w;
        }
#pragma unroll
        for (int t = 0; t < B4; t++) {
            int idx = t * 256 + tid;
            int r = idx / bc4;
            int c4 = idx % bc4;
            float4 v = *(const float4*)(B + (size_t)(k0 + r) * Ncol + colBase + c4 * 4);
            *(float4*)&Bs[r][c4 * 4] = v;
        }
        __syncthreads();
#pragma unroll
        for (int kk = 0; kk < BK; kk++) {
            float a[TM], b[TN];
#pragma unroll
            for (int i = 0; i < TM / 4; i++) {
                float4 v = *(const float4*)&As[kk][ty * TM + i * 4];
                a[i * 4 + 0] = v.x; a[i * 4 + 1] = v.y; a[i * 4 + 2] = v.z; a[i * 4 + 3] = v.w;
            }
#pragma unroll
            for (int j = 0; j < TN / 4; j++) {
                float4 v = *(const float4*)&Bs[kk][tx * TN + j * 4];
                b[j * 4 + 0] = v.x; b[j * 4 + 1] = v.y; b[j * 4 + 2] = v.z; b[j * 4 + 3] = v.w;
            }
#pragma unroll
            for (int i = 0; i < TM; i++)
#pragma unroll
                for (int j = 0; j < TN; j++)
                    acc[i][j] = fmaf(a[i], b[j], acc[i][j]);
        }
        __syncthreads();
    }
#pragma unroll
    for (int i = 0; i < TM; i++) {
        int gr = rowBase + ty * TM + i;
        if (gr < M) {
#pragma unroll
            for (int j = 0; j < TN / 4; j++) {
                float4 v = make_float4(acc[i][j * 4 + 0], acc[i][j * 4 + 1],
                                       acc[i][j * 4 + 2], acc[i][j * 4 + 3]);
                *(float4*)(C + (size_t)gr * Ncol + colBase + tx * TN + j * 4) = v;
            }
        }
    }
}

// ---------------- attention dot products ----------------
__global__ void att1_kernel(const float* __restrict__ atts, const float* __restrict__ attd) {
    int g = blockIdx.x * blockDim.x + threadIdx.x;
    int gw = g >> 5;
    int lane = g & 31;
    if (gw >= NN * HH) return;
    int node = gw >> 2;
    int head = gw & 3;
    const float* hp = g_h1 + (size_t)node * F1 + head * CC;
    float h0 = hp[lane], h1v = hp[lane + 32];
    float s = h0 * atts[head * CC + lane] + h1v * atts[head * CC + lane + 32];
    float d = h0 * attd[head * CC + lane] + h1v * attd[head * CC + lane + 32];
    s = warpRedSum(s);
    d = warpRedSum(d);
    if (lane == 0) {
        g_as1[node * HH + head] = s;
        g_ad1[node * HH + head] = d;
    }
}

__global__ void att2_kernel(const float* __restrict__ atts, const float* __restrict__ attd) {
    int g = blockIdx.x * blockDim.x + threadIdx.x;
    int gw = g >> 5;
    int lane = g & 31;
    if (gw >= NN) return;
    const float* hp = g_h2 + (size_t)gw * OC;
    float h0 = hp[lane], h1v = hp[lane + 32];
    float s = h0 * atts[lane] + h1v * atts[lane + 32];
    float d = h0 * attd[lane] + h1v * attd[lane + 32];
    s = warpRedSum(s);
    d = warpRedSum(d);
    if (lane == 0) {
        g_as2[gw] = s;
        g_ad2[gw] = d;
    }
}

// ---------------- per (sorted) edge alpha ----------------
__global__ void alpha1_kernel() {
    int p = blockIdx.x * blockDim.x + threadIdx.x;
    if (p >= ET) return;
    int s = g_srcs[p], d = g_dsts[p];
    float4 a;
    a.x = lrelu(g_as1[s * 4 + 0] + g_ad1[d * 4 + 0]);
    a.y = lrelu(g_as1[s * 4 + 1] + g_ad1[d * 4 + 1]);
    a.z = lrelu(g_as1[s * 4 + 2] + g_ad1[d * 4 + 2]);
    a.w = lrelu(g_as1[s * 4 + 3] + g_ad1[d * 4 + 3]);
    g_alpha1[p] = a;
}

__global__ void alpha2_kernel() {
    int p = blockIdx.x * blockDim.x + threadIdx.x;
    if (p >= ET) return;
    g_alpha2[p] = lrelu(g_as2[g_srcs[p]] + g_ad2[g_dsts[p]]);
}

// ---------------- layer-1 aggregation (block per dst, no atomics) ----------------
__global__ __launch_bounds__(256)
void agg1_kernel(const float* __restrict__ bias) {
    int n = blockIdx.x;
    int tid = threadIdx.x;
    int lane = tid & 31, wid = tid >> 5;
    int beg = g_off[n];
    int deg = g_off[n + 1] - beg;

    __shared__ float s_mx[4], s_rd[4];
    __shared__ float red[32];
    const float NEG = __int_as_float(0xff800000);

    // pass 1: per-head max
    float4 mx = make_float4(NEG, NEG, NEG, NEG);
    for (int i = tid; i < deg; i += 256) {
        float4 a = g_alpha1[beg + i];
        mx.x = fmaxf(mx.x, a.x); mx.y = fmaxf(mx.y, a.y);
        mx.z = fmaxf(mx.z, a.z); mx.w = fmaxf(mx.w, a.w);
    }
    mx.x = warpRedMax(mx.x); mx.y = warpRedMax(mx.y);
    mx.z = warpRedMax(mx.z); mx.w = warpRedMax(mx.w);
    if (lane == 0) {
        red[wid * 4 + 0] = mx.x; red[wid * 4 + 1] = mx.y;
        red[wid * 4 + 2] = mx.z; red[wid * 4 + 3] = mx.w;
    }
    __syncthreads();
    if (tid < 4) {
        float m = red[tid];
        for (int w = 1; w < 8; w++) m = fmaxf(m, red[w * 4 + tid]);
        s_mx[tid] = m;
    }
    __syncthreads();
    float4 M = make_float4(s_mx[0], s_mx[1], s_mx[2], s_mx[3]);

    // pass 2: per-head denom
    float4 sm = make_float4(0.f, 0.f, 0.f, 0.f);
    for (int i = tid; i < deg; i += 256) {
        float4 a = g_alpha1[beg + i];
        sm.x += __expf(a.x - M.x); sm.y += __expf(a.y - M.y);
        sm.z += __expf(a.z - M.z); sm.w += __expf(a.w - M.w);
    }
    sm.x = warpRedSum(sm.x); sm.y = warpRedSum(sm.y);
    sm.z = warpRedSum(sm.z); sm.w = warpRedSum(sm.w);
    __syncthreads();
    if (lane == 0) {
        red[wid * 4 + 0] = sm.x; red[wid * 4 + 1] = sm.y;
        red[wid * 4 + 2] = sm.z; red[wid * 4 + 3] = sm.w;
    }
    __syncthreads();
    if (tid < 4) {
        float ssum = red[tid];
        for (int w = 1; w < 8; w++) ssum += red[w * 4 + tid];
        s_rd[tid] = 1.f / (ssum + 1e-16f);
    }
    __syncthreads();

    // pass 3: gather + weighted accumulate (each thread owns one of 256 channels)
    __shared__ int s_src[64];
    __shared__ float s_coef[256];
    int head = tid >> 6;
    float acc = 0.f;
    for (int ch = 0; ch < deg; ch += 64) {
        int m = min(64, deg - ch);
        if (tid < m) s_src[tid] = g_srcs[beg + ch + tid];
        if (tid < m * 4) {
            int i = tid >> 2, h = tid & 3;
            const float* ap = (const float*)&g_alpha1[beg + ch + i];
            s_coef[tid] = __expf(ap[h] - s_mx[h]) * s_rd[h];
        }
        __syncthreads();
        int i = 0;
        for (; i + 4 <= m; i += 4) {
            float v0 = g_h1[(size_t)s_src[i + 0] * F1 + tid];
            float v1 = g_h1[(size_t)s_src[i + 1] * F1 + tid];
            float v2 = g_h1[(size_t)s_src[i + 2] * F1 + tid];
            float v3 = g_h1[(size_t)s_src[i + 3] * F1 + tid];
            acc = fmaf(v0, s_coef[(i + 0) * 4 + head], acc);
            acc = fmaf(v1, s_coef[(i + 1) * 4 + head], acc);
            acc = fmaf(v2, s_coef[(i + 2) * 4 + head], acc);
            acc = fmaf(v3, s_coef[(i + 3) * 4 + head], acc);
        }
        for (; i < m; i++)
            acc = fmaf(g_h1[(size_t)s_src[i] * F1 + tid], s_coef[i * 4 + head], acc);
        __syncthreads();
    }
    float v = acc + bias[tid];
    g_x1[(size_t)n * F1 + tid] = fmaxf(v, 0.f);   // fused relu
}

// ---------------- layer-2 aggregation + bias + log_softmax ----------------
__global__ __launch_bounds__(64)
void agg2_kernel(const float* __restrict__ bias, float* __restrict__ out) {
    int n = blockIdx.x, tid = threadIdx.x;
    int lane = tid & 31, wid = tid >> 5;
    int beg = g_off[n];
    int deg = g_off[n + 1] - beg;
    __shared__ float red[2];
    __shared__ float s_mx, s_rd;
    const float NEG = __int_as_float(0xff800000);

    float mx = NEG;
    for (int i = tid; i < deg; i += 64) mx = fmaxf(mx, g_alpha2[beg + i]);
    mx = warpRedMax(mx);
    if (lane == 0) red[wid] = mx;
    __syncthreads();
    if (tid == 0) s_mx = fmaxf(red[0], red[1]);
    __syncthreads();
    float M = s_mx;

    float sm = 0.f;
    for (int i = tid; i < deg; i += 64) sm += __expf(g_alpha2[beg + i] - M);
    sm = warpRedSum(sm);
    __syncthreads();
    if (lane == 0) red[wid] = sm;
    __syncthreads();
    if (tid == 0) s_rd = 1.f / ((red[0] + red[1]) + 1e-16f);
    __syncthreads();
    float rd = s_rd;

    __shared__ int s_src[64];
    __shared__ float s_coef[64];
    float acc = 0.f;
    for (int ch = 0; ch < deg; ch += 64) {
        int m = min(64, deg - ch);
        if (tid < m) {
            s_src[tid] = g_srcs[beg + ch + tid];
            s_coef[tid] = __expf(g_alpha2[beg + ch + tid] - M) * rd;
        }
        __syncthreads();
        for (int i = 0; i < m; i++)
            acc = fmaf(g_h2[(size_t)s_src[i] * OC + tid], s_coef[i], acc);
        __syncthreads();
    }
    float v = acc + bias[tid];

    // fused log_softmax over 64 channels
    float vm = warpRedMax(v);
    if (lane == 0) red[wid] = vm;
    __syncthreads();
    float MM = fmaxf(red[0], red[1]);
    __syncthreads();
    float e = __expf(v - MM);
    float es = warpRedSum(e);
    if (lane == 0) red[wid] = es;
    __syncthreads();
    float S = red[0] + red[1];
    out[(size_t)n * OC + tid] = v - MM - logf(S);
}

// ---------------- launch ----------------
extern "C" void kernel_launch(void* const* d_in, const int* in_sizes, int n_in,
                              void* d_out, int out_size) {
    const float* x        = (const float*)d_in[0];
    const void*  ei       = d_in[1];
    const float* W1       = (const float*)d_in[2];
    const float* att_src1 = (const float*)d_in[3];
    const float* att_dst1 = (const float*)d_in[4];
    const float* b1       = (const float*)d_in[5];
    const float* W2       = (const float*)d_in[6];
    const float* att_src2 = (const float*)d_in[7];
    const float* att_dst2 = (const float*)d_in[8];
    const float* b2       = (const float*)d_in[9];
    float* out            = (float*)d_out;

    void *p_h1, *p_x1, *p_h2;
    cudaGetSymbolAddress(&p_h1, g_h1);
    cudaGetSymbolAddress(&p_x1, g_x1);
    cudaGetSymbolAddress(&p_h2, g_h2);

    // CSR build (independent of GEMM — issued first)
    detect_kernel<<<1, 32>>>(ei);
    zero_deg_kernel<<<(NN + 255) / 256, 256>>>();
    count_kernel<<<(ET + 255) / 256, 256>>>(ei);
    scan_kernel<<<1, 1024>>>();
    fill_kernel<<<(ET + 255) / 256, 256>>>(ei);

    // layer 1
    sgemm_kernel<128, 128, 16, 8, 8>
        <<<dim3(F1 / 128, (NN + 127) / 128), 256>>>(x, W1, (float*)p_h1, NN, F1, 256);
    att1_kernel<<<((size_t)NN * HH * 32 + 255) / 256, 256>>>(att_src1, att_dst1);
    alpha1_kernel<<<(ET + 255) / 256, 256>>>();
    agg1_kernel<<<NN, 256>>>(b1);

    // layer 2
    sgemm_kernel<128, 64, 16, 8, 4>
        <<<dim3(OC / 64, (NN + 127) / 128), 256>>>((const float*)p_x1, W2, (float*)p_h2, NN, OC, F1);
    att2_kernel<<<((size_t)NN * 32 + 255) / 256, 256>>>(att_src2, att_dst2);
    alpha2_kernel<<<(ET + 255) / 256, 256>>>();
    agg2_kernel<<<NN, 64>>>(b2, out);
}

// round 3
// speedup vs baseline: 1.2342x; 1.2342x over previous
#include <cuda_runtime.h>
#include <cuda_bf16.h>
#include <math.h>

// Problem constants
#define NN 50000
#define EE 800000
#define ET 850000   // EE + NN self loops
#define F1 256      // HEADS*HID
#define HH 4
#define CC 64
#define OC 64
#define NB 196      // ceil(NN/256)

// ---------------- device scratch ----------------
__device__ float  g_h1[(size_t)NN * F1];   // x @ W1
__device__ float  g_x1[(size_t)NN * F1];   // layer-1 output (post relu+bias)
__device__ float  g_h2[(size_t)NN * OC];   // x1 @ W2
__device__ float  g_as1[NN * HH];
__device__ float  g_ad1[NN * HH];
__device__ float  g_as2[NN];
__device__ float  g_ad2[NN];
__device__ int    g_deg[NB * 256];
__device__ int    g_off[NN + 1];
__device__ int    g_pos[NN];
__device__ int    g_srcs[ET];
__device__ int    g_bsum[256];
__device__ int    g_boff[256];
__device__ int    g_is64;

// ---------------- helpers ----------------
__device__ __forceinline__ float warpRedSum(float v) {
#pragma unroll
    for (int o = 16; o; o >>= 1) v += __shfl_down_sync(0xffffffffu, v, o);
    return v;
}
__device__ __forceinline__ float warpRedMax(float v) {
#pragma unroll
    for (int o = 16; o; o >>= 1) v = fmaxf(v, __shfl_down_sync(0xffffffffu, v, o));
    return v;
}
__device__ __forceinline__ float lrelu(float x) { return x > 0.f ? x : 0.2f * x; }

__device__ __forceinline__ int load_edge(const void* eiv, int idx) {
    if (g_is64) return (int)((const long long*)eiv)[idx];
    return ((const int*)eiv)[idx];
}

// ---------------- dtype sniff ----------------
__global__ void detect_kernel(const void* eiv) {
    if (threadIdx.x == 0) {
        const long long* p = (const long long*)eiv;
        int ok = 1;
        for (int i = 0; i < 256; i++) {
            long long v = p[i];
            if (v < 0 || v >= NN) { ok = 0; break; }
        }
        g_is64 = ok;
    }
}

// ---------------- CSR build ----------------
__global__ void zero_deg_kernel() {
    int i = blockIdx.x * blockDim.x + threadIdx.x;
    if (i < NB * 256) g_deg[i] = 0;
}

__global__ void count_kernel(const void* __restrict__ eiv) {
    int e = blockIdx.x * blockDim.x + threadIdx.x;
    if (e >= ET) return;
    int dst = (e < EE) ? load_edge(eiv, EE + e) : (e - EE);
    atomicAdd(&g_deg[dst], 1);
}

// phase 1: per-block sums (256 elems each)
__global__ void scan_partial_kernel() {
    int tid = threadIdx.x;
    int lane = tid & 31, wid = tid >> 5;
    int v = g_deg[blockIdx.x * 256 + tid];
    int s = v;
#pragma unroll
    for (int o = 16; o; o >>= 1) s += __shfl_down_sync(0xffffffffu, s, o);
    __shared__ int ws[8];
    if (lane == 0) ws[wid] = s;
    __syncthreads();
    if (tid == 0) {
        int t = 0;
#pragma unroll
        for (int w = 0; w < 8; w++) t += ws[w];
        g_bsum[blockIdx.x] = t;
    }
}

// phase 2: exclusive scan of NB block sums (single block)
__global__ void scan_top_kernel() {
    int tid = threadIdx.x;
    int lane = tid & 31, wid = tid >> 5;
    int d = (tid < NB) ? g_bsum[tid] : 0;
    int v = d;
#pragma unroll
    for (int o = 1; o < 32; o <<= 1) {
        int u = __shfl_up_sync(0xffffffffu, v, o);
        if (lane >= o) v += u;
    }
    __shared__ int ws[8];
    if (lane == 31) ws[wid] = v;
    __syncthreads();
    __shared__ int wo[8];
    if (tid == 0) {
        int r = 0;
#pragma unroll
        for (int w = 0; w < 8; w++) { wo[w] = r; r += ws[w]; }
    }
    __syncthreads();
    if (tid < NB) g_boff[tid] = v - d + wo[wid];
}

// phase 3: per-block exclusive scan + write offsets
__global__ void scan_write_kernel() {
    int tid = threadIdx.x;
    int lane = tid & 31, wid = tid >> 5;
    int i = blockIdx.x * 256 + tid;
    int d = g_deg[i];   // padded region is 0
    int v = d;
#pragma unroll
    for (int o = 1; o < 32; o <<= 1) {
        int u = __shfl_up_sync(0xffffffffu, v, o);
        if (lane >= o) v += u;
    }
    __shared__ int ws[8];
    if (lane == 31) ws[wid] = v;
    __syncthreads();
    __shared__ int wo[8];
    if (tid == 0) {
        int r = 0;
#pragma unroll
        for (int w = 0; w < 8; w++) { wo[w] = r; r += ws[w]; }
    }
    __syncthreads();
    int excl = v - d + wo[wid] + g_boff[blockIdx.x];
    if (i < NN) {
        g_off[i] = excl;
        g_pos[i] = excl;
        if (i == NN - 1) g_off[NN] = excl + d;
    }
}

__global__ void fill_kernel(const void* __restrict__ eiv) {
    int e = blockIdx.x * blockDim.x + threadIdx.x;
    if (e >= ET) return;
    int src, dst;
    if (e < EE) { src = load_edge(eiv, e); dst = load_edge(eiv, EE + e); }
    else        { src = dst = e - EE; }
    int p = atomicAdd(&g_pos[dst], 1);
    g_srcs[p] = src;
}

// ---------------- SGEMM (A:MxK row-major, B:KxN row-major, C:MxN) ----------------
template <int BM, int BN, int BK, int TM, int TN>
__global__ __launch_bounds__(256)
void sgemm_kernel(const float* __restrict__ A, const float* __restrict__ B,
                  float* __restrict__ C, int M, int Ncol, int K) {
    __shared__ float As[BK][BM];
    __shared__ float Bs[BK][BN];
    const int TX = BN / TN;
    const int tid = threadIdx.x;
    const int tx = tid % TX;
    const int ty = tid / TX;
    const int rowBase = blockIdx.y * BM;
    const int colBase = blockIdx.x * BN;

    float acc[TM][TN];
#pragma unroll
    for (int i = 0; i < TM; i++)
#pragma unroll
        for (int j = 0; j < TN; j++) acc[i][j] = 0.f;

    const int A4 = (BM * BK) / (256 * 4);
    const int B4 = (BK * BN) / (256 * 4);
    const int ac4 = BK / 4;
    const int bc4 = BN / 4;

    for (int k0 = 0; k0 < K; k0 += BK) {
#pragma unroll
        for (int t = 0; t < A4; t++) {
            int idx = t * 256 + tid;
            int r = idx / ac4;
            int c4 = idx % ac4;
            int gr = rowBase + r;
            float4 v = make_float4(0.f, 0.f, 0.f, 0.f);
            if (gr < M) v = *(const float4*)(A + (size_t)gr * K + k0 + c4 * 4);
            As[c4 * 4 + 0][r] = v.x;
            As[c4 * 4 + 1][r] = v.y;
            As[c4 * 4 + 2][r] = v.z;
            As[c4 * 4 + 3][r] = v.w;
        }
#pragma unroll
        for (int t = 0; t < B4; t++) {
            int idx = t * 256 + tid;
            int r = idx / bc4;
            int c4 = idx % bc4;
            float4 v = *(const float4*)(B + (size_t)(k0 + r) * Ncol + colBase + c4 * 4);
            *(float4*)&Bs[r][c4 * 4] = v;
        }
        __syncthreads();
#pragma unroll
        for (int kk = 0; kk < BK; kk++) {
            float a[TM], b[TN];
#pragma unroll
            for (int i = 0; i < TM / 4; i++) {
                float4 v = *(const float4*)&As[kk][ty * TM + i * 4];
                a[i * 4 + 0] = v.x; a[i * 4 + 1] = v.y; a[i * 4 + 2] = v.z; a[i * 4 + 3] = v.w;
            }
#pragma unroll
            for (int j = 0; j < TN / 4; j++) {
                float4 v = *(const float4*)&Bs[kk][tx * TN + j * 4];
                b[j * 4 + 0] = v.x; b[j * 4 + 1] = v.y; b[j * 4 + 2] = v.z; b[j * 4 + 3] = v.w;
            }
#pragma unroll
            for (int i = 0; i < TM; i++)
#pragma unroll
                for (int j = 0; j < TN; j++)
                    acc[i][j] = fmaf(a[i], b[j], acc[i][j]);
        }
        __syncthreads();
    }
#pragma unroll
    for (int i = 0; i < TM; i++) {
        int gr = rowBase + ty * TM + i;
        if (gr < M) {
#pragma unroll
            for (int j = 0; j < TN / 4; j++) {
                float4 v = make_float4(acc[i][j * 4 + 0], acc[i][j * 4 + 1],
                                       acc[i][j * 4 + 2], acc[i][j * 4 + 3]);
                *(float4*)(C + (size_t)gr * Ncol + colBase + tx * TN + j * 4) = v;
            }
        }
    }
}

// ---------------- attention dot products ----------------
__global__ void att1_kernel(const float* __restrict__ atts, const float* __restrict__ attd) {
    int g = blockIdx.x * blockDim.x + threadIdx.x;
    int gw = g >> 5;
    int lane = g & 31;
    if (gw >= NN * HH) return;
    int node = gw >> 2;
    int head = gw & 3;
    const float* hp = g_h1 + (size_t)node * F1 + head * CC;
    float h0 = hp[lane], h1v = hp[lane + 32];
    float s = h0 * atts[head * CC + lane] + h1v * atts[head * CC + lane + 32];
    float d = h0 * attd[head * CC + lane] + h1v * attd[head * CC + lane + 32];
    s = warpRedSum(s);
    d = warpRedSum(d);
    if (lane == 0) {
        g_as1[node * HH + head] = s;
        g_ad1[node * HH + head] = d;
    }
}

__global__ void att2_kernel(const float* __restrict__ atts, const float* __restrict__ attd) {
    int g = blockIdx.x * blockDim.x + threadIdx.x;
    int gw = g >> 5;
    int lane = g & 31;
    if (gw >= NN) return;
    const float* hp = g_h2 + (size_t)gw * OC;
    float h0 = hp[lane], h1v = hp[lane + 32];
    float s = h0 * atts[lane] + h1v * atts[lane + 32];
    float d = h0 * attd[lane] + h1v * attd[lane + 32];
    s = warpRedSum(s);
    d = warpRedSum(d);
    if (lane == 0) {
        g_as2[gw] = s;
        g_ad2[gw] = d;
    }
}

// ---------------- layer-1 aggregation (block per dst, no atomics, on-the-fly alpha) ----------------
__global__ __launch_bounds__(256)
void agg1_kernel(const float* __restrict__ bias) {
    int n = blockIdx.x;
    int tid = threadIdx.x;
    int lane = tid & 31, wid = tid >> 5;
    int beg = g_off[n];
    int deg = g_off[n + 1] - beg;

    float4 ad = *(const float4*)&g_ad1[n * 4];

    __shared__ float s_rd[4];
    __shared__ float red[32];

    // pass 1: denom = sum exp(lrelu(as[src]+ad))   (no max shift; |alpha| << 88)
    float4 sm = make_float4(0.f, 0.f, 0.f, 0.f);
    for (int i = tid; i < deg; i += 256) {
        int s = g_srcs[beg + i];
        float4 as = *(const float4*)&g_as1[s * 4];
        sm.x += __expf(lrelu(as.x + ad.x));
        sm.y += __expf(lrelu(as.y + ad.y));
        sm.z += __expf(lrelu(as.z + ad.z));
        sm.w += __expf(lrelu(as.w + ad.w));
    }
    sm.x = warpRedSum(sm.x); sm.y = warpRedSum(sm.y);
    sm.z = warpRedSum(sm.z); sm.w = warpRedSum(sm.w);
    if (lane == 0) {
        red[wid * 4 + 0] = sm.x; red[wid * 4 + 1] = sm.y;
        red[wid * 4 + 2] = sm.z; red[wid * 4 + 3] = sm.w;
    }
    __syncthreads();
    if (tid < 4) {
        float ssum = red[tid];
        for (int w = 1; w < 8; w++) ssum += red[w * 4 + tid];
        s_rd[tid] = 1.f / (ssum + 1e-16f);
    }
    __syncthreads();

    // pass 2: gather + weighted accumulate (each thread owns one of 256 channels)
    __shared__ int s_src[64];
    __shared__ float s_coef[256];
    int head = tid >> 6;
    float adh = ((const float*)&ad)[tid & 3];
    float acc = 0.f;
    for (int ch = 0; ch < deg; ch += 64) {
        int m = min(64, deg - ch);
        if (tid < m) s_src[tid] = g_srcs[beg + ch + tid];
        if (tid < m * 4) {
            int i = tid >> 2, h = tid & 3;
            int s = g_srcs[beg + ch + i];
            s_coef[tid] = __expf(lrelu(g_as1[s * 4 + h] + adh)) * s_rd[h];
        }
        __syncthreads();
        int i = 0;
        for (; i + 4 <= m; i += 4) {
            float v0 = g_h1[(size_t)s_src[i + 0] * F1 + tid];
            float v1 = g_h1[(size_t)s_src[i + 1] * F1 + tid];
            float v2 = g_h1[(size_t)s_src[i + 2] * F1 + tid];
            float v3 = g_h1[(size_t)s_src[i + 3] * F1 + tid];
            acc = fmaf(v0, s_coef[(i + 0) * 4 + head], acc);
            acc = fmaf(v1, s_coef[(i + 1) * 4 + head], acc);
            acc = fmaf(v2, s_coef[(i + 2) * 4 + head], acc);
            acc = fmaf(v3, s_coef[(i + 3) * 4 + head], acc);
        }
        for (; i < m; i++)
            acc = fmaf(g_h1[(size_t)s_src[i] * F1 + tid], s_coef[i * 4 + head], acc);
        __syncthreads();
    }
    float v = acc + bias[tid];
    g_x1[(size_t)n * F1 + tid] = fmaxf(v, 0.f);   // fused relu
}

// ---------------- layer-2 aggregation + bias + log_softmax ----------------
__global__ __launch_bounds__(64)
void agg2_kernel(const float* __restrict__ bias, float* __restrict__ out) {
    int n = blockIdx.x, tid = threadIdx.x;
    int lane = tid & 31, wid = tid >> 5;
    int beg = g_off[n];
    int deg = g_off[n + 1] - beg;
    __shared__ float red[2];
    __shared__ float s_rd;

    float ad = g_ad2[n];

    float sm = 0.f;
    for (int i = tid; i < deg; i += 64)
        sm += __expf(lrelu(g_as2[g_srcs[beg + i]] + ad));
    sm = warpRedSum(sm);
    if (lane == 0) red[wid] = sm;
    __syncthreads();
    if (tid == 0) s_rd = 1.f / ((red[0] + red[1]) + 1e-16f);
    __syncthreads();
    float rd = s_rd;

    __shared__ int s_src[64];
    __shared__ float s_coef[64];
    float acc = 0.f;
    for (int ch = 0; ch < deg; ch += 64) {
        int m = min(64, deg - ch);
        if (tid < m) {
            int s = g_srcs[beg + ch + tid];
            s_src[tid] = s;
            s_coef[tid] = __expf(lrelu(g_as2[s] + ad)) * rd;
        }
        __syncthreads();
        for (int i = 0; i < m; i++)
            acc = fmaf(g_h2[(size_t)s_src[i] * OC + tid], s_coef[i], acc);
        __syncthreads();
    }
    float v = acc + bias[tid];

    // fused log_softmax over 64 channels
    float vm = warpRedMax(v);
    if (lane == 0) red[wid] = vm;
    __syncthreads();
    float MM = fmaxf(red[0], red[1]);
    __syncthreads();
    float e = __expf(v - MM);
    float es = warpRedSum(e);
    if (lane == 0) red[wid] = es;
    __syncthreads();
    float S = red[0] + red[1];
    out[(size_t)n * OC + tid] = v - MM - logf(S);
}

// ---------------- launch ----------------
extern "C" void kernel_launch(void* const* d_in, const int* in_sizes, int n_in,
                              void* d_out, int out_size) {
    const float* x        = (const float*)d_in[0];
    const void*  ei       = d_in[1];
    const float* W1       = (const float*)d_in[2];
    const float* att_src1 = (const float*)d_in[3];
    const float* att_dst1 = (const float*)d_in[4];
    const float* b1       = (const float*)d_in[5];
    const float* W2       = (const float*)d_in[6];
    const float* att_src2 = (const float*)d_in[7];
    const float* att_dst2 = (const float*)d_in[8];
    const float* b2       = (const float*)d_in[9];
    float* out            = (float*)d_out;

    void *p_h1, *p_x1, *p_h2;
    cudaGetSymbolAddress(&p_h1, g_h1);
    cudaGetSymbolAddress(&p_x1, g_x1);
    cudaGetSymbolAddress(&p_h2, g_h2);

    // CSR build
    detect_kernel<<<1, 32>>>(ei);
    zero_deg_kernel<<<NB, 256>>>();
    count_kernel<<<(ET + 255) / 256, 256>>>(ei);
    scan_partial_kernel<<<NB, 256>>>();
    scan_top_kernel<<<1, 256>>>();
    scan_write_kernel<<<NB, 256>>>();
    fill_kernel<<<(ET + 255) / 256, 256>>>(ei);

    // layer 1
    sgemm_kernel<128, 128, 16, 8, 8>
        <<<dim3(F1 / 128, (NN + 127) / 128), 256>>>(x, W1, (float*)p_h1, NN, F1, 256);
    att1_kernel<<<((size_t)NN * HH * 32 + 255) / 256, 256>>>(att_src1, att_dst1);
    agg1_kernel<<<NN, 256>>>(b1);

    // layer 2
    sgemm_kernel<128, 64, 16, 8, 4>
        <<<dim3(OC / 64, (NN + 127) / 128), 256>>>((const float*)p_x1, W2, (float*)p_h2, NN, OC, F1);
    att2_kernel<<<((size_t)NN * 32 + 255) / 256, 256>>>(att_src2, att_dst2);
    agg2_kernel<<<NN, 64>>>(b2, out);
}

// round 4
// speedup vs baseline: 1.6517x; 1.3383x over previous
#include <cuda_runtime.h>
#include <cuda_bf16.h>
#include <math.h>
#include <stdint.h>

// Problem constants
#define NN 50000
#define EE 800000
#define ET 850000   // EE + NN self loops
#define F1 256      // HEADS*HID
#define HH 4
#define CC 64
#define OC 64
#define NB 196      // ceil(NN/256)

// ---------------- device scratch ----------------
__device__ float  g_h1[(size_t)NN * F1];   // x @ W1
__device__ float  g_x1[(size_t)NN * F1];   // layer-1 output (post relu+bias)
__device__ float  g_h2[(size_t)NN * OC];   // x1 @ W2
__device__ float  g_as1[NN * HH];
__device__ float  g_ad1[NN * HH];
__device__ float  g_as2[NN];
__device__ float  g_ad2[NN];
__device__ int    g_deg[NB * 256];
__device__ int    g_off[NN + 1];
__device__ int    g_pos[NN];
__device__ int    g_srcs[ET];
__device__ int    g_bsum[256];
__device__ int    g_boff[256];
__device__ int    g_is64;

// ---------------- helpers ----------------
__device__ __forceinline__ float warpRedSum(float v) {
#pragma unroll
    for (int o = 16; o; o >>= 1) v += __shfl_down_sync(0xffffffffu, v, o);
    return v;
}
__device__ __forceinline__ float warpRedMax(float v) {
#pragma unroll
    for (int o = 16; o; o >>= 1) v = fmaxf(v, __shfl_down_sync(0xffffffffu, v, o));
    return v;
}
__device__ __forceinline__ float lrelu(float x) { return x > 0.f ? x : 0.2f * x; }

__device__ __forceinline__ int load_edge(const void* eiv, int idx) {
    if (g_is64) return (int)((const long long*)eiv)[idx];
    return ((const int*)eiv)[idx];
}

__device__ __forceinline__ uint32_t f2tf32(float f) {
    uint32_t u;
    asm("cvt.rna.tf32.f32 %0, %1;" : "=r"(u) : "f"(f));
    return u;
}

__device__ __forceinline__ void mma_tf32(float c[4],
                                         uint32_t a0, uint32_t a1, uint32_t a2, uint32_t a3,
                                         uint32_t b0, uint32_t b1) {
    asm volatile(
        "mma.sync.aligned.m16n8k8.row.col.f32.tf32.tf32.f32 "
        "{%0,%1,%2,%3},{%4,%5,%6,%7},{%8,%9},{%0,%1,%2,%3};"
        : "+f"(c[0]), "+f"(c[1]), "+f"(c[2]), "+f"(c[3])
        : "r"(a0), "r"(a1), "r"(a2), "r"(a3), "r"(b0), "r"(b1));
}

// ---------------- dtype sniff ----------------
__global__ void detect_kernel(const void* eiv) {
    if (threadIdx.x == 0) {
        const long long* p = (const long long*)eiv;
        int ok = 1;
        for (int i = 0; i < 256; i++) {
            long long v = p[i];
            if (v < 0 || v >= NN) { ok = 0; break; }
        }
        g_is64 = ok;
    }
}

// ---------------- CSR build ----------------
__global__ void zero_deg_kernel() {
    int i = blockIdx.x * blockDim.x + threadIdx.x;
    if (i < NB * 256) g_deg[i] = 0;
}

__global__ void count_kernel(const void* __restrict__ eiv) {
    int e = blockIdx.x * blockDim.x + threadIdx.x;
    if (e >= ET) return;
    int dst = (e < EE) ? load_edge(eiv, EE + e) : (e - EE);
    atomicAdd(&g_deg[dst], 1);
}

__global__ void scan_partial_kernel() {
    int tid = threadIdx.x;
    int lane = tid & 31, wid = tid >> 5;
    int v = g_deg[blockIdx.x * 256 + tid];
    int s = v;
#pragma unroll
    for (int o = 16; o; o >>= 1) s += __shfl_down_sync(0xffffffffu, s, o);
    __shared__ int ws[8];
    if (lane == 0) ws[wid] = s;
    __syncthreads();
    if (tid == 0) {
        int t = 0;
#pragma unroll
        for (int w = 0; w < 8; w++) t += ws[w];
        g_bsum[blockIdx.x] = t;
    }
}

__global__ void scan_top_kernel() {
    int tid = threadIdx.x;
    int lane = tid & 31, wid = tid >> 5;
    int d = (tid < NB) ? g_bsum[tid] : 0;
    int v = d;
#pragma unroll
    for (int o = 1; o < 32; o <<= 1) {
        int u = __shfl_up_sync(0xffffffffu, v, o);
        if (lane >= o) v += u;
    }
    __shared__ int ws[8];
    if (lane == 31) ws[wid] = v;
    __syncthreads();
    __shared__ int wo[8];
    if (tid == 0) {
        int r = 0;
#pragma unroll
        for (int w = 0; w < 8; w++) { wo[w] = r; r += ws[w]; }
    }
    __syncthreads();
    if (tid < NB) g_boff[tid] = v - d + wo[wid];
}

__global__ void scan_write_kernel() {
    int tid = threadIdx.x;
    int lane = tid & 31, wid = tid >> 5;
    int i = blockIdx.x * 256 + tid;
    int d = g_deg[i];
    int v = d;
#pragma unroll
    for (int o = 1; o < 32; o <<= 1) {
        int u = __shfl_up_sync(0xffffffffu, v, o);
        if (lane >= o) v += u;
    }
    __shared__ int ws[8];
    if (lane == 31) ws[wid] = v;
    __syncthreads();
    __shared__ int wo[8];
    if (tid == 0) {
        int r = 0;
#pragma unroll
        for (int w = 0; w < 8; w++) { wo[w] = r; r += ws[w]; }
    }
    __syncthreads();
    int excl = v - d + wo[wid] + g_boff[blockIdx.x];
    if (i < NN) {
        g_off[i] = excl;
        g_pos[i] = excl;
        if (i == NN - 1) g_off[NN] = excl + d;
    }
}

__global__ void fill_kernel(const void* __restrict__ eiv) {
    int e = blockIdx.x * blockDim.x + threadIdx.x;
    if (e >= ET) return;
    int src, dst;
    if (e < EE) { src = load_edge(eiv, e); dst = load_edge(eiv, EE + e); }
    else        { src = dst = e - EE; }
    int p = atomicAdd(&g_pos[dst], 1);
    g_srcs[p] = src;
}

// ---------------- TF32 tensor-core GEMM ----------------
// A: MxK row-major fp32, B: KxN row-major fp32, C: MxN fp32.
// BM=128, BK=32, 256 threads (8 warps: 2 along M x 4 along N).
template <int BM, int BN>
__global__ __launch_bounds__(256)
void tf32_gemm_kernel(const float* __restrict__ A, const float* __restrict__ B,
                      float* __restrict__ C, int M, int Ncol, int K) {
    constexpr int BK = 32;
    constexpr int PAD = 4;
    constexpr int WN = BN / 4;     // warp tile N
    constexpr int MT = 4;          // 4 x m16 = 64 rows per warp
    constexpr int NT = WN / 8;     // n8 tiles per warp
    constexpr int A_LD = (BM * BK) / (256 * 4);
    constexpr int B_LD = (BK * BN) / (256 * 4);
    constexpr int BB4 = BN / 4;

    __shared__ uint32_t As[BM][BK + PAD];
    __shared__ uint32_t Bs[BK][BN + PAD];

    const int tid = threadIdx.x;
    const int lane = tid & 31, wid = tid >> 5;
    const int wm = wid & 1, wn = wid >> 1;
    const int g = lane >> 2, tg = lane & 3;
    const int rowBase = blockIdx.y * BM;
    const int colBase = blockIdx.x * BN;

    float acc[MT][NT][4];
#pragma unroll
    for (int i = 0; i < MT; i++)
#pragma unroll
        for (int j = 0; j < NT; j++)
#pragma unroll
            for (int t = 0; t < 4; t++) acc[i][j][t] = 0.f;

    float4 ra[A_LD], rb[B_LD];

    // initial global loads
#pragma unroll
    for (int t = 0; t < A_LD; t++) {
        int idx = t * 256 + tid;
        int r = idx >> 3, c = idx & 7;
        int row = rowBase + r;
        ra[t] = (row < M) ? *(const float4*)(A + (size_t)row * K + c * 4)
                          : make_float4(0.f, 0.f, 0.f, 0.f);
    }
#pragma unroll
    for (int t = 0; t < B_LD; t++) {
        int idx = t * 256 + tid;
        int r = idx / BB4, c = idx % BB4;
        rb[t] = *(const float4*)(B + (size_t)r * Ncol + colBase + c * 4);
    }

    for (int k0 = 0; k0 < K; k0 += BK) {
        // store staged tile to smem (tf32 bits)
#pragma unroll
        for (int t = 0; t < A_LD; t++) {
            int idx = t * 256 + tid;
            int r = idx >> 3, c = idx & 7;
            As[r][c * 4 + 0] = f2tf32(ra[t].x);
            As[r][c * 4 + 1] = f2tf32(ra[t].y);
            As[r][c * 4 + 2] = f2tf32(ra[t].z);
            As[r][c * 4 + 3] = f2tf32(ra[t].w);
        }
#pragma unroll
        for (int t = 0; t < B_LD; t++) {
            int idx = t * 256 + tid;
            int r = idx / BB4, c = idx % BB4;
            Bs[r][c * 4 + 0] = f2tf32(rb[t].x);
            Bs[r][c * 4 + 1] = f2tf32(rb[t].y);
            Bs[r][c * 4 + 2] = f2tf32(rb[t].z);
            Bs[r][c * 4 + 3] = f2tf32(rb[t].w);
        }
        __syncthreads();

        // prefetch next tile into registers
        int kn = k0 + BK;
        if (kn < K) {
#pragma unroll
            for (int t = 0; t < A_LD; t++) {
                int idx = t * 256 + tid;
                int r = idx >> 3, c = idx & 7;
                int row = rowBase + r;
                ra[t] = (row < M) ? *(const float4*)(A + (size_t)row * K + kn + c * 4)
                                  : make_float4(0.f, 0.f, 0.f, 0.f);
            }
#pragma unroll
            for (int t = 0; t < B_LD; t++) {
                int idx = t * 256 + tid;
                int r = idx / BB4, c = idx % BB4;
                rb[t] = *(const float4*)(B + (size_t)(kn + r) * Ncol + colBase + c * 4);
            }
        }

        // compute: 4 k8 steps
#pragma unroll
        for (int ks = 0; ks < 4; ks++) {
            int kb = ks * 8;
            uint32_t af[MT][4];
#pragma unroll
            for (int mt = 0; mt < MT; mt++) {
                int r0 = wm * 64 + mt * 16 + g;
                af[mt][0] = As[r0][kb + tg];
                af[mt][1] = As[r0 + 8][kb + tg];
                af[mt][2] = As[r0][kb + tg + 4];
                af[mt][3] = As[r0 + 8][kb + tg + 4];
            }
            uint32_t bf[NT][2];
#pragma unroll
            for (int nt = 0; nt < NT; nt++) {
                int n = wn * WN + nt * 8 + g;
                bf[nt][0] = Bs[kb + tg][n];
                bf[nt][1] = Bs[kb + tg + 4][n];
            }
#pragma unroll
            for (int mt = 0; mt < MT; mt++)
#pragma unroll
                for (int nt = 0; nt < NT; nt++)
                    mma_tf32(acc[mt][nt], af[mt][0], af[mt][1], af[mt][2], af[mt][3],
                             bf[nt][0], bf[nt][1]);
        }
        __syncthreads();
    }

    // epilogue
#pragma unroll
    for (int mt = 0; mt < MT; mt++) {
#pragma unroll
        for (int nt = 0; nt < NT; nt++) {
            int row = rowBase + wm * 64 + mt * 16 + g;
            int col = colBase + wn * WN + nt * 8 + tg * 2;
            if (row < M)
                *(float2*)(C + (size_t)row * Ncol + col) =
                    make_float2(acc[mt][nt][0], acc[mt][nt][1]);
            if (row + 8 < M)
                *(float2*)(C + (size_t)(row + 8) * Ncol + col) =
                    make_float2(acc[mt][nt][2], acc[mt][nt][3]);
        }
    }
}

// ---------------- attention dot products ----------------
__global__ void att1_kernel(const float* __restrict__ atts, const float* __restrict__ attd) {
    int g = blockIdx.x * blockDim.x + threadIdx.x;
    int gw = g >> 5;
    int lane = g & 31;
    if (gw >= NN * HH) return;
    int node = gw >> 2;
    int head = gw & 3;
    const float* hp = g_h1 + (size_t)node * F1 + head * CC;
    float h0 = hp[lane], h1v = hp[lane + 32];
    float s = h0 * atts[head * CC + lane] + h1v * atts[head * CC + lane + 32];
    float d = h0 * attd[head * CC + lane] + h1v * attd[head * CC + lane + 32];
    s = warpRedSum(s);
    d = warpRedSum(d);
    if (lane == 0) {
        g_as1[node * HH + head] = s;
        g_ad1[node * HH + head] = d;
    }
}

__global__ void att2_kernel(const float* __restrict__ atts, const float* __restrict__ attd) {
    int g = blockIdx.x * blockDim.x + threadIdx.x;
    int gw = g >> 5;
    int lane = g & 31;
    if (gw >= NN) return;
    const float* hp = g_h2 + (size_t)gw * OC;
    float h0 = hp[lane], h1v = hp[lane + 32];
    float s = h0 * atts[lane] + h1v * atts[lane + 32];
    float d = h0 * attd[lane] + h1v * attd[lane + 32];
    s = warpRedSum(s);
    d = warpRedSum(d);
    if (lane == 0) {
        g_as2[gw] = s;
        g_ad2[gw] = d;
    }
}

// ---------------- layer-1 aggregation ----------------
__global__ __launch_bounds__(256)
void agg1_kernel(const float* __restrict__ bias) {
    int n = blockIdx.x;
    int tid = threadIdx.x;
    int lane = tid & 31, wid = tid >> 5;
    int beg = g_off[n];
    int deg = g_off[n + 1] - beg;

    float4 ad = *(const float4*)&g_ad1[n * 4];

    __shared__ float s_rd[4];
    __shared__ float red[32];

    float4 sm = make_float4(0.f, 0.f, 0.f, 0.f);
    for (int i = tid; i < deg; i += 256) {
        int s = g_srcs[beg + i];
        float4 as = *(const float4*)&g_as1[s * 4];
        sm.x += __expf(lrelu(as.x + ad.x));
        sm.y += __expf(lrelu(as.y + ad.y));
        sm.z += __expf(lrelu(as.z + ad.z));
        sm.w += __expf(lrelu(as.w + ad.w));
    }
    sm.x = warpRedSum(sm.x); sm.y = warpRedSum(sm.y);
    sm.z = warpRedSum(sm.z); sm.w = warpRedSum(sm.w);
    if (lane == 0) {
        red[wid * 4 + 0] = sm.x; red[wid * 4 + 1] = sm.y;
        red[wid * 4 + 2] = sm.z; red[wid * 4 + 3] = sm.w;
    }
    __syncthreads();
    if (tid < 4) {
        float ssum = red[tid];
        for (int w = 1; w < 8; w++) ssum += red[w * 4 + tid];
        s_rd[tid] = 1.f / (ssum + 1e-16f);
    }
    __syncthreads();

    __shared__ int s_src[64];
    __shared__ float s_coef[256];
    int head = tid >> 6;
    float adh = ((const float*)&ad)[tid & 3];
    float acc = 0.f;
    for (int ch = 0; ch < deg; ch += 64) {
        int m = min(64, deg - ch);
        if (tid < m) s_src[tid] = g_srcs[beg + ch + tid];
        if (tid < m * 4) {
            int i = tid >> 2, h = tid & 3;
            int s = g_srcs[beg + ch + i];
            s_coef[tid] = __expf(lrelu(g_as1[s * 4 + h] + adh)) * s_rd[h];
        }
        __syncthreads();
        int i = 0;
        for (; i + 4 <= m; i += 4) {
            float v0 = g_h1[(size_t)s_src[i + 0] * F1 + tid];
            float v1 = g_h1[(size_t)s_src[i + 1] * F1 + tid];
            float v2 = g_h1[(size_t)s_src[i + 2] * F1 + tid];
            float v3 = g_h1[(size_t)s_src[i + 3] * F1 + tid];
            acc = fmaf(v0, s_coef[(i + 0) * 4 + head], acc);
            acc = fmaf(v1, s_coef[(i + 1) * 4 + head], acc);
            acc = fmaf(v2, s_coef[(i + 2) * 4 + head], acc);
            acc = fmaf(v3, s_coef[(i + 3) * 4 + head], acc);
        }
        for (; i < m; i++)
            acc = fmaf(g_h1[(size_t)s_src[i] * F1 + tid], s_coef[i * 4 + head], acc);
        __syncthreads();
    }
    float v = acc + bias[tid];
    g_x1[(size_t)n * F1 + tid] = fmaxf(v, 0.f);
}

// ---------------- layer-2 aggregation + bias + log_softmax ----------------
__global__ __launch_bounds__(64)
void agg2_kernel(const float* __restrict__ bias, float* __restrict__ out) {
    int n = blockIdx.x, tid = threadIdx.x;
    int lane = tid & 31, wid = tid >> 5;
    int beg = g_off[n];
    int deg = g_off[n + 1] - beg;
    __shared__ float red[2];
    __shared__ float s_rd;

    float ad = g_ad2[n];

    float sm = 0.f;
    for (int i = tid; i < deg; i += 64)
        sm += __expf(lrelu(g_as2[g_srcs[beg + i]] + ad));
    sm = warpRedSum(sm);
    if (lane == 0) red[wid] = sm;
    __syncthreads();
    if (tid == 0) s_rd = 1.f / ((red[0] + red[1]) + 1e-16f);
    __syncthreads();
    float rd = s_rd;

    __shared__ int s_src[64];
    __shared__ float s_coef[64];
    float acc = 0.f;
    for (int ch = 0; ch < deg; ch += 64) {
        int m = min(64, deg - ch);
        if (tid < m) {
            int s = g_srcs[beg + ch + tid];
            s_src[tid] = s;
            s_coef[tid] = __expf(lrelu(g_as2[s] + ad)) * rd;
        }
        __syncthreads();
        for (int i = 0; i < m; i++)
            acc = fmaf(g_h2[(size_t)s_src[i] * OC + tid], s_coef[i], acc);
        __syncthreads();
    }
    float v = acc + bias[tid];

    float vm = warpRedMax(v);
    if (lane == 0) red[wid] = vm;
    __syncthreads();
    float MM = fmaxf(red[0], red[1]);
    __syncthreads();
    float e = __expf(v - MM);
    float es = warpRedSum(e);
    if (lane == 0) red[wid] = es;
    __syncthreads();
    float S = red[0] + red[1];
    out[(size_t)n * OC + tid] = v - MM - logf(S);
}

// ---------------- launch ----------------
extern "C" void kernel_launch(void* const* d_in, const int* in_sizes, int n_in,
                              void* d_out, int out_size) {
    const float* x        = (const float*)d_in[0];
    const void*  ei       = d_in[1];
    const float* W1       = (const float*)d_in[2];
    const float* att_src1 = (const float*)d_in[3];
    const float* att_dst1 = (const float*)d_in[4];
    const float* b1       = (const float*)d_in[5];
    const float* W2       = (const float*)d_in[6];
    const float* att_src2 = (const float*)d_in[7];
    const float* att_dst2 = (const float*)d_in[8];
    const float* b2       = (const float*)d_in[9];
    float* out            = (float*)d_out;

    void *p_h1, *p_x1, *p_h2;
    cudaGetSymbolAddress(&p_h1, g_h1);
    cudaGetSymbolAddress(&p_x1, g_x1);
    cudaGetSymbolAddress(&p_h2, g_h2);

    // CSR build
    detect_kernel<<<1, 32>>>(ei);
    zero_deg_kernel<<<NB, 256>>>();
    count_kernel<<<(ET + 255) / 256, 256>>>(ei);
    scan_partial_kernel<<<NB, 256>>>();
    scan_top_kernel<<<1, 256>>>();
    scan_write_kernel<<<NB, 256>>>();
    fill_kernel<<<(ET + 255) / 256, 256>>>(ei);

    // layer 1
    tf32_gemm_kernel<128, 128>
        <<<dim3(F1 / 128, (NN + 127) / 128), 256>>>(x, W1, (float*)p_h1, NN, F1, 256);
    att1_kernel<<<((size_t)NN * HH * 32 + 255) / 256, 256>>>(att_src1, att_dst1);
    agg1_kernel<<<NN, 256>>>(b1);

    // layer 2
    tf32_gemm_kernel<128, 64>
        <<<dim3(OC / 64, (NN + 127) / 128), 256>>>((const float*)p_x1, W2, (float*)p_h2, NN, OC, F1);
    att2_kernel<<<((size_t)NN * 32 + 255) / 256, 256>>>(att_src2, att_dst2);
    agg2_kernel<<<NN, 64>>>(b2, out);
}

// round 5
// speedup vs baseline: 2.0335x; 1.2311x over previous
#include <cuda_runtime.h>
#include <cuda_bf16.h>
#include <math.h>
#include <stdint.h>

// Problem constants
#define NN 50000
#define EE 800000
#define ET 850000   // EE + NN self loops
#define F1 256      // HEADS*HID
#define HH 4
#define CC 64
#define OC 64
#define NB 196      // ceil(NN/256)

// ---------------- device scratch ----------------
__device__ float  g_h1[(size_t)NN * F1];   // x @ W1
__device__ float  g_x1[(size_t)NN * F1];   // layer-1 output (post relu+bias)
__device__ float  g_h2[(size_t)NN * OC];   // x1 @ W2
__device__ float  g_as1[NN * HH];
__device__ float  g_ad1[NN * HH];
__device__ float  g_as2[NN];
__device__ float  g_ad2[NN];
__device__ int    g_deg[NB * 256];
__device__ int    g_off[NN + 1];
__device__ int    g_pos[NN];
__device__ int    g_srcs[ET];
__device__ int    g_bsum[256];
__device__ int    g_boff[256];
__device__ int    g_is64;

// ---------------- helpers ----------------
__device__ __forceinline__ float warpRedSum(float v) {
#pragma unroll
    for (int o = 16; o; o >>= 1) v += __shfl_down_sync(0xffffffffu, v, o);
    return v;
}
__device__ __forceinline__ float warpRedMax(float v) {
#pragma unroll
    for (int o = 16; o; o >>= 1) v = fmaxf(v, __shfl_down_sync(0xffffffffu, v, o));
    return v;
}
__device__ __forceinline__ float lrelu(float x) { return x > 0.f ? x : 0.2f * x; }

__device__ __forceinline__ int load_edge(const void* eiv, int idx) {
    if (g_is64) return (int)((const long long*)eiv)[idx];
    return ((const int*)eiv)[idx];
}

__device__ __forceinline__ uint32_t f2tf32(float f) {
    uint32_t u;
    asm("cvt.rna.tf32.f32 %0, %1;" : "=r"(u) : "f"(f));
    return u;
}

__device__ __forceinline__ void mma_tf32(float c[4],
                                         uint32_t a0, uint32_t a1, uint32_t a2, uint32_t a3,
                                         uint32_t b0, uint32_t b1) {
    asm volatile(
        "mma.sync.aligned.m16n8k8.row.col.f32.tf32.tf32.f32 "
        "{%0,%1,%2,%3},{%4,%5,%6,%7},{%8,%9},{%0,%1,%2,%3};"
        : "+f"(c[0]), "+f"(c[1]), "+f"(c[2]), "+f"(c[3])
        : "r"(a0), "r"(a1), "r"(a2), "r"(a3), "r"(b0), "r"(b1));
}

// ---------------- dtype sniff ----------------
__global__ void detect_kernel(const void* eiv) {
    if (threadIdx.x == 0) {
        const long long* p = (const long long*)eiv;
        int ok = 1;
        for (int i = 0; i < 256; i++) {
            long long v = p[i];
            if (v < 0 || v >= NN) { ok = 0; break; }
        }
        g_is64 = ok;
    }
}

// ---------------- CSR build ----------------
__global__ void zero_deg_kernel() {
    int i = blockIdx.x * blockDim.x + threadIdx.x;
    if (i < NB * 256) g_deg[i] = 0;
}

__global__ void count_kernel(const void* __restrict__ eiv) {
    int e = blockIdx.x * blockDim.x + threadIdx.x;
    if (e >= ET) return;
    int dst = (e < EE) ? load_edge(eiv, EE + e) : (e - EE);
    atomicAdd(&g_deg[dst], 1);
}

__global__ void scan_partial_kernel() {
    int tid = threadIdx.x;
    int lane = tid & 31, wid = tid >> 5;
    int v = g_deg[blockIdx.x * 256 + tid];
    int s = v;
#pragma unroll
    for (int o = 16; o; o >>= 1) s += __shfl_down_sync(0xffffffffu, s, o);
    __shared__ int ws[8];
    if (lane == 0) ws[wid] = s;
    __syncthreads();
    if (tid == 0) {
        int t = 0;
#pragma unroll
        for (int w = 0; w < 8; w++) t += ws[w];
        g_bsum[blockIdx.x] = t;
    }
}

__global__ void scan_top_kernel() {
    int tid = threadIdx.x;
    int lane = tid & 31, wid = tid >> 5;
    int d = (tid < NB) ? g_bsum[tid] : 0;
    int v = d;
#pragma unroll
    for (int o = 1; o < 32; o <<= 1) {
        int u = __shfl_up_sync(0xffffffffu, v, o);
        if (lane >= o) v += u;
    }
    __shared__ int ws[8];
    if (lane == 31) ws[wid] = v;
    __syncthreads();
    __shared__ int wo[8];
    if (tid == 0) {
        int r = 0;
#pragma unroll
        for (int w = 0; w < 8; w++) { wo[w] = r; r += ws[w]; }
    }
    __syncthreads();
    if (tid < NB) g_boff[tid] = v - d + wo[wid];
}

__global__ void scan_write_kernel() {
    int tid = threadIdx.x;
    int lane = tid & 31, wid = tid >> 5;
    int i = blockIdx.x * 256 + tid;
    int d = g_deg[i];
    int v = d;
#pragma unroll
    for (int o = 1; o < 32; o <<= 1) {
        int u = __shfl_up_sync(0xffffffffu, v, o);
        if (lane >= o) v += u;
    }
    __shared__ int ws[8];
    if (lane == 31) ws[wid] = v;
    __syncthreads();
    __shared__ int wo[8];
    if (tid == 0) {
        int r = 0;
#pragma unroll
        for (int w = 0; w < 8; w++) { wo[w] = r; r += ws[w]; }
    }
    __syncthreads();
    int excl = v - d + wo[wid] + g_boff[blockIdx.x];
    if (i < NN) {
        g_off[i] = excl;
        g_pos[i] = excl;
        if (i == NN - 1) g_off[NN] = excl + d;
    }
}

__global__ void fill_kernel(const void* __restrict__ eiv) {
    int e = blockIdx.x * blockDim.x + threadIdx.x;
    if (e >= ET) return;
    int src, dst;
    if (e < EE) { src = load_edge(eiv, e); dst = load_edge(eiv, EE + e); }
    else        { src = dst = e - EE; }
    int p = atomicAdd(&g_pos[dst], 1);
    g_srcs[p] = src;
}

// ---------------- TF32 tensor-core GEMM ----------------
template <int BM, int BN>
__global__ __launch_bounds__(256)
void tf32_gemm_kernel(const float* __restrict__ A, const float* __restrict__ B,
                      float* __restrict__ C, int M, int Ncol, int K) {
    constexpr int BK = 32;
    constexpr int PAD = 4;
    constexpr int WN = BN / 4;
    constexpr int MT = 4;
    constexpr int NT = WN / 8;
    constexpr int A_LD = (BM * BK) / (256 * 4);
    constexpr int B_LD = (BK * BN) / (256 * 4);
    constexpr int BB4 = BN / 4;

    __shared__ uint32_t As[BM][BK + PAD];
    __shared__ uint32_t Bs[BK][BN + PAD];

    const int tid = threadIdx.x;
    const int lane = tid & 31, wid = tid >> 5;
    const int wm = wid & 1, wn = wid >> 1;
    const int g = lane >> 2, tg = lane & 3;
    const int rowBase = blockIdx.y * BM;
    const int colBase = blockIdx.x * BN;

    float acc[MT][NT][4];
#pragma unroll
    for (int i = 0; i < MT; i++)
#pragma unroll
        for (int j = 0; j < NT; j++)
#pragma unroll
            for (int t = 0; t < 4; t++) acc[i][j][t] = 0.f;

    float4 ra[A_LD], rb[B_LD];

#pragma unroll
    for (int t = 0; t < A_LD; t++) {
        int idx = t * 256 + tid;
        int r = idx >> 3, c = idx & 7;
        int row = rowBase + r;
        ra[t] = (row < M) ? *(const float4*)(A + (size_t)row * K + c * 4)
                          : make_float4(0.f, 0.f, 0.f, 0.f);
    }
#pragma unroll
    for (int t = 0; t < B_LD; t++) {
        int idx = t * 256 + tid;
        int r = idx / BB4, c = idx % BB4;
        rb[t] = *(const float4*)(B + (size_t)r * Ncol + colBase + c * 4);
    }

    for (int k0 = 0; k0 < K; k0 += BK) {
#pragma unroll
        for (int t = 0; t < A_LD; t++) {
            int idx = t * 256 + tid;
            int r = idx >> 3, c = idx & 7;
            As[r][c * 4 + 0] = f2tf32(ra[t].x);
            As[r][c * 4 + 1] = f2tf32(ra[t].y);
            As[r][c * 4 + 2] = f2tf32(ra[t].z);
            As[r][c * 4 + 3] = f2tf32(ra[t].w);
        }
#pragma unroll
        for (int t = 0; t < B_LD; t++) {
            int idx = t * 256 + tid;
            int r = idx / BB4, c = idx % BB4;
            Bs[r][c * 4 + 0] = f2tf32(rb[t].x);
            Bs[r][c * 4 + 1] = f2tf32(rb[t].y);
            Bs[r][c * 4 + 2] = f2tf32(rb[t].z);
            Bs[r][c * 4 + 3] = f2tf32(rb[t].w);
        }
        __syncthreads();

        int kn = k0 + BK;
        if (kn < K) {
#pragma unroll
            for (int t = 0; t < A_LD; t++) {
                int idx = t * 256 + tid;
                int r = idx >> 3, c = idx & 7;
                int row = rowBase + r;
                ra[t] = (row < M) ? *(const float4*)(A + (size_t)row * K + kn + c * 4)
                                  : make_float4(0.f, 0.f, 0.f, 0.f);
            }
#pragma unroll
            for (int t = 0; t < B_LD; t++) {
                int idx = t * 256 + tid;
                int r = idx / BB4, c = idx % BB4;
                rb[t] = *(const float4*)(B + (size_t)(kn + r) * Ncol + colBase + c * 4);
            }
        }

#pragma unroll
        for (int ks = 0; ks < 4; ks++) {
            int kb = ks * 8;
            uint32_t af[MT][4];
#pragma unroll
            for (int mt = 0; mt < MT; mt++) {
                int r0 = wm * 64 + mt * 16 + g;
                af[mt][0] = As[r0][kb + tg];
                af[mt][1] = As[r0 + 8][kb + tg];
                af[mt][2] = As[r0][kb + tg + 4];
                af[mt][3] = As[r0 + 8][kb + tg + 4];
            }
            uint32_t bf[NT][2];
#pragma unroll
            for (int nt = 0; nt < NT; nt++) {
                int n = wn * WN + nt * 8 + g;
                bf[nt][0] = Bs[kb + tg][n];
                bf[nt][1] = Bs[kb + tg + 4][n];
            }
#pragma unroll
            for (int mt = 0; mt < MT; mt++)
#pragma unroll
                for (int nt = 0; nt < NT; nt++)
                    mma_tf32(acc[mt][nt], af[mt][0], af[mt][1], af[mt][2], af[mt][3],
                             bf[nt][0], bf[nt][1]);
        }
        __syncthreads();
    }

#pragma unroll
    for (int mt = 0; mt < MT; mt++) {
#pragma unroll
        for (int nt = 0; nt < NT; nt++) {
            int row = rowBase + wm * 64 + mt * 16 + g;
            int col = colBase + wn * WN + nt * 8 + tg * 2;
            if (row < M)
                *(float2*)(C + (size_t)row * Ncol + col) =
                    make_float2(acc[mt][nt][0], acc[mt][nt][1]);
            if (row + 8 < M)
                *(float2*)(C + (size_t)(row + 8) * Ncol + col) =
                    make_float2(acc[mt][nt][2], acc[mt][nt][3]);
        }
    }
}

// ---------------- attention dot products ----------------
__global__ void att1_kernel(const float* __restrict__ atts, const float* __restrict__ attd) {
    int g = blockIdx.x * blockDim.x + threadIdx.x;
    int gw = g >> 5;
    int lane = g & 31;
    if (gw >= NN * HH) return;
    int node = gw >> 2;
    int head = gw & 3;
    const float* hp = g_h1 + (size_t)node * F1 + head * CC;
    float h0 = hp[lane], h1v = hp[lane + 32];
    float s = h0 * atts[head * CC + lane] + h1v * atts[head * CC + lane + 32];
    float d = h0 * attd[head * CC + lane] + h1v * attd[head * CC + lane + 32];
    s = warpRedSum(s);
    d = warpRedSum(d);
    if (lane == 0) {
        g_as1[node * HH + head] = s;
        g_ad1[node * HH + head] = d;
    }
}

__global__ void att2_kernel(const float* __restrict__ atts, const float* __restrict__ attd) {
    int g = blockIdx.x * blockDim.x + threadIdx.x;
    int gw = g >> 5;
    int lane = g & 31;
    if (gw >= NN) return;
    const float* hp = g_h2 + (size_t)gw * OC;
    float h0 = hp[lane], h1v = hp[lane + 32];
    float s = h0 * atts[lane] + h1v * atts[lane + 32];
    float d = h0 * attd[lane] + h1v * attd[lane + 32];
    s = warpRedSum(s);
    d = warpRedSum(d);
    if (lane == 0) {
        g_as2[gw] = s;
        g_ad2[gw] = d;
    }
}

// ---------------- layer-1 aggregation: SINGLE pass, normalize at end ----------------
__global__ __launch_bounds__(256)
void agg1_kernel(const float* __restrict__ bias) {
    int n = blockIdx.x;
    int tid = threadIdx.x;
    int lane = tid & 31, wid = tid >> 5;
    int beg = g_off[n];
    int deg = g_off[n + 1] - beg;

    float4 ad = *(const float4*)&g_ad1[n * 4];

    __shared__ int s_src[64];
    __shared__ float s_coef[256];
    __shared__ float red[32];
    __shared__ float s_rd[4];

    int head = tid >> 6;
    float adh = ((const float*)&ad)[tid & 3];
    float acc = 0.f;
    float dpart = 0.f;   // partial denominator for head (tid&3)

    for (int ch = 0; ch < deg; ch += 64) {
        int m = min(64, deg - ch);
        if (tid < m) s_src[tid] = g_srcs[beg + ch + tid];
        if (tid < m * 4) {
            int i = tid >> 2, h = tid & 3;
            int s = g_srcs[beg + ch + i];
            float w = __expf(lrelu(g_as1[s * 4 + h] + adh));
            s_coef[tid] = w;
            dpart += w;
        }
        __syncthreads();
        int i = 0;
        for (; i + 4 <= m; i += 4) {
            float v0 = g_h1[(size_t)s_src[i + 0] * F1 + tid];
            float v1 = g_h1[(size_t)s_src[i + 1] * F1 + tid];
            float v2 = g_h1[(size_t)s_src[i + 2] * F1 + tid];
            float v3 = g_h1[(size_t)s_src[i + 3] * F1 + tid];
            acc = fmaf(v0, s_coef[(i + 0) * 4 + head], acc);
            acc = fmaf(v1, s_coef[(i + 1) * 4 + head], acc);
            acc = fmaf(v2, s_coef[(i + 2) * 4 + head], acc);
            acc = fmaf(v3, s_coef[(i + 3) * 4 + head], acc);
        }
        for (; i < m; i++)
            acc = fmaf(g_h1[(size_t)s_src[i] * F1 + tid], s_coef[i * 4 + head], acc);
        __syncthreads();
    }

    // reduce denominator: lanes hold heads in (lane&3) pattern
    dpart += __shfl_down_sync(0xffffffffu, dpart, 16);
    dpart += __shfl_down_sync(0xffffffffu, dpart, 8);
    dpart += __shfl_down_sync(0xffffffffu, dpart, 4);
    if (lane < 4) red[wid * 4 + lane] = dpart;
    __syncthreads();
    if (tid < 4) {
        float s = red[tid];
        for (int w = 1; w < 8; w++) s += red[w * 4 + tid];
        s_rd[tid] = 1.f / (s + 1e-16f);
    }
    __syncthreads();

    float v = acc * s_rd[head] + bias[tid];
    g_x1[(size_t)n * F1 + tid] = fmaxf(v, 0.f);
}

// ---------------- layer-2 aggregation: SINGLE pass + bias + log_softmax ----------------
__global__ __launch_bounds__(64)
void agg2_kernel(const float* __restrict__ bias, float* __restrict__ out) {
    int n = blockIdx.x, tid = threadIdx.x;
    int lane = tid & 31, wid = tid >> 5;
    int beg = g_off[n];
    int deg = g_off[n + 1] - beg;
    __shared__ float red[2];
    __shared__ int s_src[64];
    __shared__ float s_coef[64];

    float ad = g_ad2[n];
    float acc = 0.f;
    float dpart = 0.f;

    for (int ch = 0; ch < deg; ch += 64) {
        int m = min(64, deg - ch);
        if (tid < m) {
            int s = g_srcs[beg + ch + tid];
            s_src[tid] = s;
            float w = __expf(lrelu(g_as2[s] + ad));
            s_coef[tid] = w;
            dpart += w;
        }
        __syncthreads();
        for (int i = 0; i < m; i++)
            acc = fmaf(g_h2[(size_t)s_src[i] * OC + tid], s_coef[i], acc);
        __syncthreads();
    }

    float dsum = warpRedSum(dpart);
    if (lane == 0) red[wid] = dsum;
    __syncthreads();
    float rd = 1.f / ((red[0] + red[1]) + 1e-16f);

    float v = acc * rd + bias[tid];

    // fused log_softmax over 64 channels
    __syncthreads();
    float vm = warpRedMax(v);
    if (lane == 0) red[wid] = vm;
    __syncthreads();
    float MM = fmaxf(red[0], red[1]);
    __syncthreads();
    float e = __expf(v - MM);
    float es = warpRedSum(e);
    if (lane == 0) red[wid] = es;
    __syncthreads();
    float S = red[0] + red[1];
    out[(size_t)n * OC + tid] = v - MM - logf(S);
}

// ---------------- launch ----------------
static cudaStream_t s_side = 0;
static cudaEvent_t  s_evFork = 0, s_evJoin = 0;

extern "C" void kernel_launch(void* const* d_in, const int* in_sizes, int n_in,
                              void* d_out, int out_size) {
    const float* x        = (const float*)d_in[0];
    const void*  ei       = d_in[1];
    const float* W1       = (const float*)d_in[2];
    const float* att_src1 = (const float*)d_in[3];
    const float* att_dst1 = (const float*)d_in[4];
    const float* b1       = (const float*)d_in[5];
    const float* W2       = (const float*)d_in[6];
    const float* att_src2 = (const float*)d_in[7];
    const float* att_dst2 = (const float*)d_in[8];
    const float* b2       = (const float*)d_in[9];
    float* out            = (float*)d_out;

    if (!s_side) {
        cudaStreamCreateWithFlags(&s_side, cudaStreamNonBlocking);
        cudaEventCreateWithFlags(&s_evFork, cudaEventDisableTiming);
        cudaEventCreateWithFlags(&s_evJoin, cudaEventDisableTiming);
    }

    void *p_h1, *p_x1, *p_h2;
    cudaGetSymbolAddress(&p_h1, g_h1);
    cudaGetSymbolAddress(&p_x1, g_x1);
    cudaGetSymbolAddress(&p_h2, g_h2);

    // fork: CSR build on side stream, concurrent with GEMM1/att1 on main
    cudaEventRecord(s_evFork, 0);
    cudaStreamWaitEvent(s_side, s_evFork, 0);

    detect_kernel<<<1, 32, 0, s_side>>>(ei);
    zero_deg_kernel<<<NB, 256, 0, s_side>>>();
    count_kernel<<<(ET + 255) / 256, 256, 0, s_side>>>(ei);
    scan_partial_kernel<<<NB, 256, 0, s_side>>>();
    scan_top_kernel<<<1, 256, 0, s_side>>>();
    scan_write_kernel<<<NB, 256, 0, s_side>>>();
    fill_kernel<<<(ET + 255) / 256, 256, 0, s_side>>>(ei);
    cudaEventRecord(s_evJoin, s_side);

    // main stream: layer-1 dense work
    tf32_gemm_kernel<128, 128>
        <<<dim3(F1 / 128, (NN + 127) / 128), 256>>>(x, W1, (float*)p_h1, NN, F1, 256);
    att1_kernel<<<((size_t)NN * HH * 32 + 255) / 256, 256>>>(att_src1, att_dst1);

    // join: agg1 needs CSR + att1
    cudaStreamWaitEvent(0, s_evJoin, 0);
    agg1_kernel<<<NN, 256>>>(b1);

    // layer 2
    tf32_gemm_kernel<128, 64>
        <<<dim3(OC / 64, (NN + 127) / 128), 256>>>((const float*)p_x1, W2, (float*)p_h2, NN, OC, F1);
    att2_kernel<<<((size_t)NN * 32 + 255) / 256, 256>>>(att_src2, att_dst2);
    agg2_kernel<<<NN, 64>>>(b2, out);
}

// round 6
// speedup vs baseline: 2.1033x; 1.0343x over previous
#include <cuda_runtime.h>
#include <cuda_bf16.h>
#include <math.h>
#include <stdint.h>

// Problem constants
#define NN 50000
#define EE 800000
#define ET 850000   // EE + NN self loops
#define F1 256      // HEADS*HID
#define HH 4
#define CC 64
#define OC 64
#define NB 196      // ceil(NN/256)

// ---------------- device scratch ----------------
__device__ __nv_bfloat16 g_h1b[(size_t)NN * F1];  // x @ W1 (bf16)
__device__ float  g_x1[(size_t)NN * F1];          // layer-1 output (post relu+bias)
__device__ __nv_bfloat16 g_h2b[(size_t)NN * OC];  // x1 @ W2 (bf16)
__device__ float  g_as1[NN * HH];
__device__ float  g_ad1[NN * HH];
__device__ float  g_as2[NN];
__device__ float  g_ad2[NN];
__device__ int    g_deg[NB * 256];
__device__ int    g_off[NN + 1];
__device__ int    g_pos[NN];
__device__ int    g_srcs[ET];
__device__ int    g_bsum[256];
__device__ int    g_boff[256];
__device__ int    g_is64;

// ---------------- helpers ----------------
__device__ __forceinline__ float warpRedSum(float v) {
#pragma unroll
    for (int o = 16; o; o >>= 1) v += __shfl_down_sync(0xffffffffu, v, o);
    return v;
}
__device__ __forceinline__ float warpRedMax(float v) {
#pragma unroll
    for (int o = 16; o; o >>= 1) v = fmaxf(v, __shfl_down_sync(0xffffffffu, v, o));
    return v;
}
__device__ __forceinline__ float lrelu(float x) { return x > 0.f ? x : 0.2f * x; }

__device__ __forceinline__ int load_edge(const void* eiv, int idx) {
    if (g_is64) return (int)((const long long*)eiv)[idx];
    return ((const int*)eiv)[idx];
}

__device__ __forceinline__ uint32_t f2tf32(float f) {
    uint32_t u;
    asm("cvt.rna.tf32.f32 %0, %1;" : "=r"(u) : "f"(f));
    return u;
}

__device__ __forceinline__ void mma_tf32(float c[4],
                                         uint32_t a0, uint32_t a1, uint32_t a2, uint32_t a3,
                                         uint32_t b0, uint32_t b1) {
    asm volatile(
        "mma.sync.aligned.m16n8k8.row.col.f32.tf32.tf32.f32 "
        "{%0,%1,%2,%3},{%4,%5,%6,%7},{%8,%9},{%0,%1,%2,%3};"
        : "+f"(c[0]), "+f"(c[1]), "+f"(c[2]), "+f"(c[3])
        : "r"(a0), "r"(a1), "r"(a2), "r"(a3), "r"(b0), "r"(b1));
}

// ---------------- dtype sniff ----------------
__global__ void detect_kernel(const void* eiv) {
    if (threadIdx.x == 0) {
        const long long* p = (const long long*)eiv;
        int ok = 1;
        for (int i = 0; i < 256; i++) {
            long long v = p[i];
            if (v < 0 || v >= NN) { ok = 0; break; }
        }
        g_is64 = ok;
    }
}

// ---------------- CSR build ----------------
__global__ void zero_deg_kernel() {
    int i = blockIdx.x * blockDim.x + threadIdx.x;
    if (i < NB * 256) g_deg[i] = 0;
}

__global__ void count_kernel(const void* __restrict__ eiv) {
    int e = blockIdx.x * blockDim.x + threadIdx.x;
    if (e >= ET) return;
    int dst = (e < EE) ? load_edge(eiv, EE + e) : (e - EE);
    atomicAdd(&g_deg[dst], 1);
}

__global__ void scan_partial_kernel() {
    int tid = threadIdx.x;
    int lane = tid & 31, wid = tid >> 5;
    int v = g_deg[blockIdx.x * 256 + tid];
    int s = v;
#pragma unroll
    for (int o = 16; o; o >>= 1) s += __shfl_down_sync(0xffffffffu, s, o);
    __shared__ int ws[8];
    if (lane == 0) ws[wid] = s;
    __syncthreads();
    if (tid == 0) {
        int t = 0;
#pragma unroll
        for (int w = 0; w < 8; w++) t += ws[w];
        g_bsum[blockIdx.x] = t;
    }
}

__global__ void scan_top_kernel() {
    int tid = threadIdx.x;
    int lane = tid & 31, wid = tid >> 5;
    int d = (tid < NB) ? g_bsum[tid] : 0;
    int v = d;
#pragma unroll
    for (int o = 1; o < 32; o <<= 1) {
        int u = __shfl_up_sync(0xffffffffu, v, o);
        if (lane >= o) v += u;
    }
    __shared__ int ws[8];
    if (lane == 31) ws[wid] = v;
    __syncthreads();
    __shared__ int wo[8];
    if (tid == 0) {
        int r = 0;
#pragma unroll
        for (int w = 0; w < 8; w++) { wo[w] = r; r += ws[w]; }
    }
    __syncthreads();
    if (tid < NB) g_boff[tid] = v - d + wo[wid];
}

__global__ void scan_write_kernel() {
    int tid = threadIdx.x;
    int lane = tid & 31, wid = tid >> 5;
    int i = blockIdx.x * 256 + tid;
    int d = g_deg[i];
    int v = d;
#pragma unroll
    for (int o = 1; o < 32; o <<= 1) {
        int u = __shfl_up_sync(0xffffffffu, v, o);
        if (lane >= o) v += u;
    }
    __shared__ int ws[8];
    if (lane == 31) ws[wid] = v;
    __syncthreads();
    __shared__ int wo[8];
    if (tid == 0) {
        int r = 0;
#pragma unroll
        for (int w = 0; w < 8; w++) { wo[w] = r; r += ws[w]; }
    }
    __syncthreads();
    int excl = v - d + wo[wid] + g_boff[blockIdx.x];
    if (i < NN) {
        g_off[i] = excl;
        g_pos[i] = excl;
        if (i == NN - 1) g_off[NN] = excl + d;
    }
}

__global__ void fill_kernel(const void* __restrict__ eiv) {
    int e = blockIdx.x * blockDim.x + threadIdx.x;
    if (e >= ET) return;
    int src, dst;
    if (e < EE) { src = load_edge(eiv, e); dst = load_edge(eiv, EE + e); }
    else        { src = dst = e - EE; }
    int p = atomicAdd(&g_pos[dst], 1);
    g_srcs[p] = src;
}

// ---------------- TF32 GEMM + fused attention dots + bf16 output ----------------
// A: MxK fp32 row-major, B: KxN fp32 row-major.
// Cb: MxN bf16.  as_out/ad_out: per-row per-head dot(att, row) — heads are
// 64-col groups; each block's column strip covers LH=BN/64 whole heads.
template <int BN>
__global__ __launch_bounds__(256)
void gemm_att_kernel(const float* __restrict__ A, const float* __restrict__ B,
                     __nv_bfloat16* __restrict__ Cb,
                     const float* __restrict__ atts, const float* __restrict__ attd,
                     float* __restrict__ as_out, float* __restrict__ ad_out,
                     int M, int Ncol, int K) {
    constexpr int BM = 128;
    constexpr int BK = 32;
    constexpr int PAD = 4;
    constexpr int WN = BN / 4;
    constexpr int MT = 4;
    constexpr int NT = WN / 8;
    constexpr int LH = BN / 64;
    constexpr int A_LD = (BM * BK) / (256 * 4);
    constexpr int B_LD = (BK * BN) / (256 * 4);
    constexpr int BB4 = BN / 4;

    __shared__ uint32_t As[BM][BK + PAD];
    __shared__ uint32_t Bs[BK][BN + PAD];
    __shared__ float s_as[BM][LH];
    __shared__ float s_ad[BM][LH];

    const int tid = threadIdx.x;
    const int lane = tid & 31, wid = tid >> 5;
    const int wm = wid & 1, wn = wid >> 1;
    const int g = lane >> 2, tg = lane & 3;
    const int rowBase = blockIdx.y * BM;
    const int colBase = blockIdx.x * BN;
    const int lh = (wn * WN) >> 6;   // this warp's local head

    float acc[MT][NT][4];
#pragma unroll
    for (int i = 0; i < MT; i++)
#pragma unroll
        for (int j = 0; j < NT; j++)
#pragma unroll
            for (int t = 0; t < 4; t++) acc[i][j][t] = 0.f;

    float4 ra[A_LD], rb[B_LD];

#pragma unroll
    for (int t = 0; t < A_LD; t++) {
        int idx = t * 256 + tid;
        int r = idx >> 3, c = idx & 7;
        int row = rowBase + r;
        ra[t] = (row < M) ? *(const float4*)(A + (size_t)row * K + c * 4)
                          : make_float4(0.f, 0.f, 0.f, 0.f);
    }
#pragma unroll
    for (int t = 0; t < B_LD; t++) {
        int idx = t * 256 + tid;
        int r = idx / BB4, c = idx % BB4;
        rb[t] = *(const float4*)(B + (size_t)r * Ncol + colBase + c * 4);
    }

    for (int k0 = 0; k0 < K; k0 += BK) {
#pragma unroll
        for (int t = 0; t < A_LD; t++) {
            int idx = t * 256 + tid;
            int r = idx >> 3, c = idx & 7;
            As[r][c * 4 + 0] = f2tf32(ra[t].x);
            As[r][c * 4 + 1] = f2tf32(ra[t].y);
            As[r][c * 4 + 2] = f2tf32(ra[t].z);
            As[r][c * 4 + 3] = f2tf32(ra[t].w);
        }
#pragma unroll
        for (int t = 0; t < B_LD; t++) {
            int idx = t * 256 + tid;
            int r = idx / BB4, c = idx % BB4;
            Bs[r][c * 4 + 0] = f2tf32(rb[t].x);
            Bs[r][c * 4 + 1] = f2tf32(rb[t].y);
            Bs[r][c * 4 + 2] = f2tf32(rb[t].z);
            Bs[r][c * 4 + 3] = f2tf32(rb[t].w);
        }
        __syncthreads();

        int kn = k0 + BK;
        if (kn < K) {
#pragma unroll
            for (int t = 0; t < A_LD; t++) {
                int idx = t * 256 + tid;
                int r = idx >> 3, c = idx & 7;
                int row = rowBase + r;
                ra[t] = (row < M) ? *(const float4*)(A + (size_t)row * K + kn + c * 4)
                                  : make_float4(0.f, 0.f, 0.f, 0.f);
            }
#pragma unroll
            for (int t = 0; t < B_LD; t++) {
                int idx = t * 256 + tid;
                int r = idx / BB4, c = idx % BB4;
                rb[t] = *(const float4*)(B + (size_t)(kn + r) * Ncol + colBase + c * 4);
            }
        }

#pragma unroll
        for (int ks = 0; ks < 4; ks++) {
            int kb = ks * 8;
            uint32_t af[MT][4];
#pragma unroll
            for (int mt = 0; mt < MT; mt++) {
                int r0 = wm * 64 + mt * 16 + g;
                af[mt][0] = As[r0][kb + tg];
                af[mt][1] = As[r0 + 8][kb + tg];
                af[mt][2] = As[r0][kb + tg + 4];
                af[mt][3] = As[r0 + 8][kb + tg + 4];
            }
            uint32_t bf[NT][2];
#pragma unroll
            for (int nt = 0; nt < NT; nt++) {
                int n = wn * WN + nt * 8 + g;
                bf[nt][0] = Bs[kb + tg][n];
                bf[nt][1] = Bs[kb + tg + 4][n];
            }
#pragma unroll
            for (int mt = 0; mt < MT; mt++)
#pragma unroll
                for (int nt = 0; nt < NT; nt++)
                    mma_tf32(acc[mt][nt], af[mt][0], af[mt][1], af[mt][2], af[mt][3],
                             bf[nt][0], bf[nt][1]);
        }
        __syncthreads();
    }

    // ---- epilogue: bf16 store ----
#pragma unroll
    for (int mt = 0; mt < MT; mt++) {
#pragma unroll
        for (int nt = 0; nt < NT; nt++) {
            int row = rowBase + wm * 64 + mt * 16 + g;
            int col = colBase + wn * WN + nt * 8 + tg * 2;
            if (row < M)
                *(__nv_bfloat162*)(Cb + (size_t)row * Ncol + col) =
                    __float22bfloat162_rn(make_float2(acc[mt][nt][0], acc[mt][nt][1]));
            if (row + 8 < M)
                *(__nv_bfloat162*)(Cb + (size_t)(row + 8) * Ncol + col) =
                    __float22bfloat162_rn(make_float2(acc[mt][nt][2], acc[mt][nt][3]));
        }
    }

    // ---- epilogue: attention dots from exact fp32 accumulators ----
    for (int i = tid; i < BM * LH; i += 256) {
        ((float*)s_as)[i] = 0.f;
        ((float*)s_ad)[i] = 0.f;
    }
    __syncthreads();

    float aS0[NT], aS1[NT], aD0[NT], aD1[NT];
#pragma unroll
    for (int nt = 0; nt < NT; nt++) {
        int c = colBase + wn * WN + nt * 8 + tg * 2;
        aS0[nt] = atts[c];  aS1[nt] = atts[c + 1];
        aD0[nt] = attd[c];  aD1[nt] = attd[c + 1];
    }
#pragma unroll
    for (int mt = 0; mt < MT; mt++) {
        float sl = 0.f, dl = 0.f, sh = 0.f, dh = 0.f;
#pragma unroll
        for (int nt = 0; nt < NT; nt++) {
            sl += acc[mt][nt][0] * aS0[nt] + acc[mt][nt][1] * aS1[nt];
            dl += acc[mt][nt][0] * aD0[nt] + acc[mt][nt][1] * aD1[nt];
            sh += acc[mt][nt][2] * aS0[nt] + acc[mt][nt][3] * aS1[nt];
            dh += acc[mt][nt][2] * aD0[nt] + acc[mt][nt][3] * aD1[nt];
        }
        sl += __shfl_down_sync(0xffffffffu, sl, 2); sl += __shfl_down_sync(0xffffffffu, sl, 1);
        dl += __shfl_down_sync(0xffffffffu, dl, 2); dl += __shfl_down_sync(0xffffffffu, dl, 1);
        sh += __shfl_down_sync(0xffffffffu, sh, 2); sh += __shfl_down_sync(0xffffffffu, sh, 1);
        dh += __shfl_down_sync(0xffffffffu, dh, 2); dh += __shfl_down_sync(0xffffffffu, dh, 1);
        if (tg == 0) {
            int lr = wm * 64 + mt * 16 + g;
            atomicAdd(&s_as[lr][lh], sl);
            atomicAdd(&s_ad[lr][lh], dl);
            atomicAdd(&s_as[lr + 8][lh], sh);
            atomicAdd(&s_ad[lr + 8][lh], dh);
        }
    }
    __syncthreads();

    int HS = Ncol >> 6;   // total heads
    int hb = colBase >> 6;
    for (int i = tid; i < BM * LH; i += 256) {
        int r = i / LH, h = i % LH;
        int gr = rowBase + r;
        if (gr < M) {
            as_out[gr * HS + hb + h] = s_as[r][h];
            ad_out[gr * HS + hb + h] = s_ad[r][h];
        }
    }
}

// ---------------- layer-1 aggregation: single pass over bf16 h1 ----------------
__global__ __launch_bounds__(256)
void agg1_kernel(const float* __restrict__ bias) {
    int n = blockIdx.x;
    int tid = threadIdx.x;
    int lane = tid & 31, wid = tid >> 5;
    int beg = g_off[n];
    int deg = g_off[n + 1] - beg;

    float4 ad = *(const float4*)&g_ad1[n * 4];

    __shared__ int s_src[64];
    __shared__ float s_coef[256];
    __shared__ float red[32];
    __shared__ float s_rd[4];

    int head = tid >> 6;
    float adh = ((const float*)&ad)[tid & 3];
    float acc = 0.f;
    float dpart = 0.f;

    for (int ch = 0; ch < deg; ch += 64) {
        int m = min(64, deg - ch);
        if (tid < m) s_src[tid] = g_srcs[beg + ch + tid];
        if (tid < m * 4) {
            int i = tid >> 2, h = tid & 3;
            int s = g_srcs[beg + ch + i];
            float w = __expf(lrelu(g_as1[s * 4 + h] + adh));
            s_coef[tid] = w;
            dpart += w;
        }
        __syncthreads();
        int i = 0;
        for (; i + 4 <= m; i += 4) {
            float v0 = __bfloat162float(g_h1b[(size_t)s_src[i + 0] * F1 + tid]);
            float v1 = __bfloat162float(g_h1b[(size_t)s_src[i + 1] * F1 + tid]);
            float v2 = __bfloat162float(g_h1b[(size_t)s_src[i + 2] * F1 + tid]);
            float v3 = __bfloat162float(g_h1b[(size_t)s_src[i + 3] * F1 + tid]);
            acc = fmaf(v0, s_coef[(i + 0) * 4 + head], acc);
            acc = fmaf(v1, s_coef[(i + 1) * 4 + head], acc);
            acc = fmaf(v2, s_coef[(i + 2) * 4 + head], acc);
            acc = fmaf(v3, s_coef[(i + 3) * 4 + head], acc);
        }
        for (; i < m; i++)
            acc = fmaf(__bfloat162float(g_h1b[(size_t)s_src[i] * F1 + tid]),
                       s_coef[i * 4 + head], acc);
        __syncthreads();
    }

    dpart += __shfl_down_sync(0xffffffffu, dpart, 16);
    dpart += __shfl_down_sync(0xffffffffu, dpart, 8);
    dpart += __shfl_down_sync(0xffffffffu, dpart, 4);
    if (lane < 4) red[wid * 4 + lane] = dpart;
    __syncthreads();
    if (tid < 4) {
        float s = red[tid];
        for (int w = 1; w < 8; w++) s += red[w * 4 + tid];
        s_rd[tid] = 1.f / (s + 1e-16f);
    }
    __syncthreads();

    float v = acc * s_rd[head] + bias[tid];
    g_x1[(size_t)n * F1 + tid] = fmaxf(v, 0.f);
}

// ---------------- layer-2 aggregation: single pass + bias + log_softmax ----------------
__global__ __launch_bounds__(64)
void agg2_kernel(const float* __restrict__ bias, float* __restrict__ out) {
    int n = blockIdx.x, tid = threadIdx.x;
    int lane = tid & 31, wid = tid >> 5;
    int beg = g_off[n];
    int deg = g_off[n + 1] - beg;
    __shared__ float red[2];
    __shared__ int s_src[64];
    __shared__ float s_coef[64];

    float ad = g_ad2[n];
    float acc = 0.f;
    float dpart = 0.f;

    for (int ch = 0; ch < deg; ch += 64) {
        int m = min(64, deg - ch);
        if (tid < m) {
            int s = g_srcs[beg + ch + tid];
            s_src[tid] = s;
            float w = __expf(lrelu(g_as2[s] + ad));
            s_coef[tid] = w;
            dpart += w;
        }
        __syncthreads();
        for (int i = 0; i < m; i++)
            acc = fmaf(__bfloat162float(g_h2b[(size_t)s_src[i] * OC + tid]),
                       s_coef[i], acc);
        __syncthreads();
    }

    float dsum = warpRedSum(dpart);
    if (lane == 0) red[wid] = dsum;
    __syncthreads();
    float rd = 1.f / ((red[0] + red[1]) + 1e-16f);

    float v = acc * rd + bias[tid];

    __syncthreads();
    float vm = warpRedMax(v);
    if (lane == 0) red[wid] = vm;
    __syncthreads();
    float MM = fmaxf(red[0], red[1]);
    __syncthreads();
    float e = __expf(v - MM);
    float es = warpRedSum(e);
    if (lane == 0) red[wid] = es;
    __syncthreads();
    float S = red[0] + red[1];
    out[(size_t)n * OC + tid] = v - MM - logf(S);
}

// ---------------- launch ----------------
static cudaStream_t s_side = 0;
static cudaEvent_t  s_evFork = 0, s_evJoin = 0;

extern "C" void kernel_launch(void* const* d_in, const int* in_sizes, int n_in,
                              void* d_out, int out_size) {
    const float* x        = (const float*)d_in[0];
    const void*  ei       = d_in[1];
    const float* W1       = (const float*)d_in[2];
    const float* att_src1 = (const float*)d_in[3];
    const float* att_dst1 = (const float*)d_in[4];
    const float* b1       = (const float*)d_in[5];
    const float* W2       = (const float*)d_in[6];
    const float* att_src2 = (const float*)d_in[7];
    const float* att_dst2 = (const float*)d_in[8];
    const float* b2       = (const float*)d_in[9];
    float* out            = (float*)d_out;

    if (!s_side) {
        cudaStreamCreateWithFlags(&s_side, cudaStreamNonBlocking);
        cudaEventCreateWithFlags(&s_evFork, cudaEventDisableTiming);
        cudaEventCreateWithFlags(&s_evJoin, cudaEventDisableTiming);
    }

    void *p_h1b, *p_x1, *p_h2b, *p_as1, *p_ad1, *p_as2, *p_ad2;
    cudaGetSymbolAddress(&p_h1b, g_h1b);
    cudaGetSymbolAddress(&p_x1, g_x1);
    cudaGetSymbolAddress(&p_h2b, g_h2b);
    cudaGetSymbolAddress(&p_as1, g_as1);
    cudaGetSymbolAddress(&p_ad1, g_ad1);
    cudaGetSymbolAddress(&p_as2, g_as2);
    cudaGetSymbolAddress(&p_ad2, g_ad2);

    // fork: CSR build on side stream, concurrent with GEMM1 on main
    cudaEventRecord(s_evFork, 0);
    cudaStreamWaitEvent(s_side, s_evFork, 0);

    detect_kernel<<<1, 32, 0, s_side>>>(ei);
    zero_deg_kernel<<<NB, 256, 0, s_side>>>();
    count_kernel<<<(ET + 255) / 256, 256, 0, s_side>>>(ei);
    scan_partial_kernel<<<NB, 256, 0, s_side>>>();
    scan_top_kernel<<<1, 256, 0, s_side>>>();
    scan_write_kernel<<<NB, 256, 0, s_side>>>();
    fill_kernel<<<(ET + 255) / 256, 256, 0, s_side>>>(ei);
    cudaEventRecord(s_evJoin, s_side);

    // main stream: layer-1 GEMM (+ fused att dots, bf16 out)
    gemm_att_kernel<128>
        <<<dim3(F1 / 128, (NN + 127) / 128), 256>>>(
            x, W1, (__nv_bfloat16*)p_h1b, att_src1, att_dst1,
            (float*)p_as1, (float*)p_ad1, NN, F1, 256);

    // join: agg1 needs CSR + GEMM1
    cudaStreamWaitEvent(0, s_evJoin, 0);
    agg1_kernel<<<NN, 256>>>(b1);

    // layer 2
    gemm_att_kernel<64>
        <<<dim3(1, (NN + 127) / 128), 256>>>(
            (const float*)p_x1, W2, (__nv_bfloat16*)p_h2b, att_src2, att_dst2,
            (float*)p_as2, (float*)p_ad2, NN, OC, F1);
    agg2_kernel<<<NN, 64>>>(b2, out);
}

// round 7
// speedup vs baseline: 2.8745x; 1.3666x over previous
#include <cuda_runtime.h>
#include <cuda_bf16.h>
#include <math.h>
#include <stdint.h>

// Problem constants
#define NN 50000
#define EE 800000
#define ET 850000   // EE + NN self loops
#define F1 256      // HEADS*HID
#define HH 4
#define CC 64
#define OC 64
#define NB 196      // ceil(NN/256)

#define FULL 0xffffffffu

// ---------------- device scratch ----------------
__device__ __nv_bfloat16 g_h1b[(size_t)NN * F1];  // x @ W1 (bf16)
__device__ float  g_x1[(size_t)NN * F1];          // layer-1 output (post relu+bias)
__device__ __nv_bfloat16 g_h2b[(size_t)NN * OC];  // x1 @ W2 (bf16)
__device__ float  g_as1[NN * HH];
__device__ float  g_ad1[NN * HH];
__device__ float  g_as2[NN];
__device__ float  g_ad2[NN];
__device__ int    g_deg[NB * 256];
__device__ int    g_off[NN + 1];
__device__ int    g_pos[NN];
__device__ int    g_srcs[ET];
__device__ int    g_bsum[256];
__device__ int    g_boff[256];
__device__ int    g_is64;

// ---------------- helpers ----------------
__device__ __forceinline__ float warpXorSum(float v) {
#pragma unroll
    for (int o = 16; o; o >>= 1) v += __shfl_xor_sync(FULL, v, o);
    return v;
}
__device__ __forceinline__ float warpXorMax(float v) {
#pragma unroll
    for (int o = 16; o; o >>= 1) v = fmaxf(v, __shfl_xor_sync(FULL, v, o));
    return v;
}
__device__ __forceinline__ float lrelu(float x) { return x > 0.f ? x : 0.2f * x; }

__device__ __forceinline__ int load_edge(const void* eiv, int idx) {
    if (g_is64) return (int)((const long long*)eiv)[idx];
    return ((const int*)eiv)[idx];
}

__device__ __forceinline__ uint32_t f2tf32(float f) {
    uint32_t u;
    asm("cvt.rna.tf32.f32 %0, %1;" : "=r"(u) : "f"(f));
    return u;
}

__device__ __forceinline__ void mma_tf32(float c[4],
                                         uint32_t a0, uint32_t a1, uint32_t a2, uint32_t a3,
                                         uint32_t b0, uint32_t b1) {
    asm volatile(
        "mma.sync.aligned.m16n8k8.row.col.f32.tf32.tf32.f32 "
        "{%0,%1,%2,%3},{%4,%5,%6,%7},{%8,%9},{%0,%1,%2,%3};"
        : "+f"(c[0]), "+f"(c[1]), "+f"(c[2]), "+f"(c[3])
        : "r"(a0), "r"(a1), "r"(a2), "r"(a3), "r"(b0), "r"(b1));
}

// ---------------- dtype sniff ----------------
__global__ void detect_kernel(const void* eiv) {
    if (threadIdx.x == 0) {
        const long long* p = (const long long*)eiv;
        int ok = 1;
        for (int i = 0; i < 256; i++) {
            long long v = p[i];
            if (v < 0 || v >= NN) { ok = 0; break; }
        }
        g_is64 = ok;
    }
}

// ---------------- CSR build ----------------
__global__ void zero_deg_kernel() {
    int i = blockIdx.x * blockDim.x + threadIdx.x;
    if (i < NB * 256) g_deg[i] = 0;
}

__global__ void count_kernel(const void* __restrict__ eiv) {
    int e = blockIdx.x * blockDim.x + threadIdx.x;
    if (e >= ET) return;
    int dst = (e < EE) ? load_edge(eiv, EE + e) : (e - EE);
    atomicAdd(&g_deg[dst], 1);
}

__global__ void scan_partial_kernel() {
    int tid = threadIdx.x;
    int lane = tid & 31, wid = tid >> 5;
    int v = g_deg[blockIdx.x * 256 + tid];
    int s = v;
#pragma unroll
    for (int o = 16; o; o >>= 1) s += __shfl_down_sync(FULL, s, o);
    __shared__ int ws[8];
    if (lane == 0) ws[wid] = s;
    __syncthreads();
    if (tid == 0) {
        int t = 0;
#pragma unroll
        for (int w = 0; w < 8; w++) t += ws[w];
        g_bsum[blockIdx.x] = t;
    }
}

__global__ void scan_top_kernel() {
    int tid = threadIdx.x;
    int lane = tid & 31, wid = tid >> 5;
    int d = (tid < NB) ? g_bsum[tid] : 0;
    int v = d;
#pragma unroll
    for (int o = 1; o < 32; o <<= 1) {
        int u = __shfl_up_sync(FULL, v, o);
        if (lane >= o) v += u;
    }
    __shared__ int ws[8];
    if (lane == 31) ws[wid] = v;
    __syncthreads();
    __shared__ int wo[8];
    if (tid == 0) {
        int r = 0;
#pragma unroll
        for (int w = 0; w < 8; w++) { wo[w] = r; r += ws[w]; }
    }
    __syncthreads();
    if (tid < NB) g_boff[tid] = v - d + wo[wid];
}

__global__ void scan_write_kernel() {
    int tid = threadIdx.x;
    int lane = tid & 31, wid = tid >> 5;
    int i = blockIdx.x * 256 + tid;
    int d = g_deg[i];
    int v = d;
#pragma unroll
    for (int o = 1; o < 32; o <<= 1) {
        int u = __shfl_up_sync(FULL, v, o);
        if (lane >= o) v += u;
    }
    __shared__ int ws[8];
    if (lane == 31) ws[wid] = v;
    __syncthreads();
    __shared__ int wo[8];
    if (tid == 0) {
        int r = 0;
#pragma unroll
        for (int w = 0; w < 8; w++) { wo[w] = r; r += ws[w]; }
    }
    __syncthreads();
    int excl = v - d + wo[wid] + g_boff[blockIdx.x];
    if (i < NN) {
        g_off[i] = excl;
        g_pos[i] = excl;
        if (i == NN - 1) g_off[NN] = excl + d;
    }
}

__global__ void fill_kernel(const void* __restrict__ eiv) {
    int e = blockIdx.x * blockDim.x + threadIdx.x;
    if (e >= ET) return;
    int src, dst;
    if (e < EE) { src = load_edge(eiv, e); dst = load_edge(eiv, EE + e); }
    else        { src = dst = e - EE; }
    int p = atomicAdd(&g_pos[dst], 1);
    g_srcs[p] = src;
}

// ---------------- TF32 GEMM + fused attention dots + bf16 output ----------------
template <int BN>
__global__ __launch_bounds__(256)
void gemm_att_kernel(const float* __restrict__ A, const float* __restrict__ B,
                     __nv_bfloat16* __restrict__ Cb,
                     const float* __restrict__ atts, const float* __restrict__ attd,
                     float* __restrict__ as_out, float* __restrict__ ad_out,
                     int M, int Ncol, int K) {
    constexpr int BM = 128;
    constexpr int BK = 32;
    constexpr int PAD = 4;
    constexpr int WN = BN / 4;
    constexpr int MT = 4;
    constexpr int NT = WN / 8;
    constexpr int LH = BN / 64;
    constexpr int A_LD = (BM * BK) / (256 * 4);
    constexpr int B_LD = (BK * BN) / (256 * 4);
    constexpr int BB4 = BN / 4;

    __shared__ uint32_t As[BM][BK + PAD];
    __shared__ uint32_t Bs[BK][BN + PAD];
    __shared__ float s_as[BM][LH];
    __shared__ float s_ad[BM][LH];

    const int tid = threadIdx.x;
    const int lane = tid & 31, wid = tid >> 5;
    const int wm = wid & 1, wn = wid >> 1;
    const int g = lane >> 2, tg = lane & 3;
    const int rowBase = blockIdx.y * BM;
    const int colBase = blockIdx.x * BN;
    const int lh = (wn * WN) >> 6;

    float acc[MT][NT][4];
#pragma unroll
    for (int i = 0; i < MT; i++)
#pragma unroll
        for (int j = 0; j < NT; j++)
#pragma unroll
            for (int t = 0; t < 4; t++) acc[i][j][t] = 0.f;

    float4 ra[A_LD], rb[B_LD];

#pragma unroll
    for (int t = 0; t < A_LD; t++) {
        int idx = t * 256 + tid;
        int r = idx >> 3, c = idx & 7;
        int row = rowBase + r;
        ra[t] = (row < M) ? *(const float4*)(A + (size_t)row * K + c * 4)
                          : make_float4(0.f, 0.f, 0.f, 0.f);
    }
#pragma unroll
    for (int t = 0; t < B_LD; t++) {
        int idx = t * 256 + tid;
        int r = idx / BB4, c = idx % BB4;
        rb[t] = *(const float4*)(B + (size_t)r * Ncol + colBase + c * 4);
    }

    for (int k0 = 0; k0 < K; k0 += BK) {
#pragma unroll
        for (int t = 0; t < A_LD; t++) {
            int idx = t * 256 + tid;
            int r = idx >> 3, c = idx & 7;
            As[r][c * 4 + 0] = f2tf32(ra[t].x);
            As[r][c * 4 + 1] = f2tf32(ra[t].y);
            As[r][c * 4 + 2] = f2tf32(ra[t].z);
            As[r][c * 4 + 3] = f2tf32(ra[t].w);
        }
#pragma unroll
        for (int t = 0; t < B_LD; t++) {
            int idx = t * 256 + tid;
            int r = idx / BB4, c = idx % BB4;
            Bs[r][c * 4 + 0] = f2tf32(rb[t].x);
            Bs[r][c * 4 + 1] = f2tf32(rb[t].y);
            Bs[r][c * 4 + 2] = f2tf32(rb[t].z);
            Bs[r][c * 4 + 3] = f2tf32(rb[t].w);
        }
        __syncthreads();

        int kn = k0 + BK;
        if (kn < K) {
#pragma unroll
            for (int t = 0; t < A_LD; t++) {
                int idx = t * 256 + tid;
                int r = idx >> 3, c = idx & 7;
                int row = rowBase + r;
                ra[t] = (row < M) ? *(const float4*)(A + (size_t)row * K + kn + c * 4)
                                  : make_float4(0.f, 0.f, 0.f, 0.f);
            }
#pragma unroll
            for (int t = 0; t < B_LD; t++) {
                int idx = t * 256 + tid;
                int r = idx / BB4, c = idx % BB4;
                rb[t] = *(const float4*)(B + (size_t)(kn + r) * Ncol + colBase + c * 4);
            }
        }

#pragma unroll
        for (int ks = 0; ks < 4; ks++) {
            int kb = ks * 8;
            uint32_t af[MT][4];
#pragma unroll
            for (int mt = 0; mt < MT; mt++) {
                int r0 = wm * 64 + mt * 16 + g;
                af[mt][0] = As[r0][kb + tg];
                af[mt][1] = As[r0 + 8][kb + tg];
                af[mt][2] = As[r0][kb + tg + 4];
                af[mt][3] = As[r0 + 8][kb + tg + 4];
            }
            uint32_t bf[NT][2];
#pragma unroll
            for (int nt = 0; nt < NT; nt++) {
                int n = wn * WN + nt * 8 + g;
                bf[nt][0] = Bs[kb + tg][n];
                bf[nt][1] = Bs[kb + tg + 4][n];
            }
#pragma unroll
            for (int mt = 0; mt < MT; mt++)
#pragma unroll
                for (int nt = 0; nt < NT; nt++)
                    mma_tf32(acc[mt][nt], af[mt][0], af[mt][1], af[mt][2], af[mt][3],
                             bf[nt][0], bf[nt][1]);
        }
        __syncthreads();
    }

    // ---- epilogue: bf16 store ----
#pragma unroll
    for (int mt = 0; mt < MT; mt++) {
#pragma unroll
        for (int nt = 0; nt < NT; nt++) {
            int row = rowBase + wm * 64 + mt * 16 + g;
            int col = colBase + wn * WN + nt * 8 + tg * 2;
            if (row < M)
                *(__nv_bfloat162*)(Cb + (size_t)row * Ncol + col) =
                    __float22bfloat162_rn(make_float2(acc[mt][nt][0], acc[mt][nt][1]));
            if (row + 8 < M)
                *(__nv_bfloat162*)(Cb + (size_t)(row + 8) * Ncol + col) =
                    __float22bfloat162_rn(make_float2(acc[mt][nt][2], acc[mt][nt][3]));
        }
    }

    // ---- epilogue: attention dots from exact fp32 accumulators ----
    for (int i = tid; i < BM * LH; i += 256) {
        ((float*)s_as)[i] = 0.f;
        ((float*)s_ad)[i] = 0.f;
    }
    __syncthreads();

    float aS0[NT], aS1[NT], aD0[NT], aD1[NT];
#pragma unroll
    for (int nt = 0; nt < NT; nt++) {
        int c = colBase + wn * WN + nt * 8 + tg * 2;
        aS0[nt] = atts[c];  aS1[nt] = atts[c + 1];
        aD0[nt] = attd[c];  aD1[nt] = attd[c + 1];
    }
#pragma unroll
    for (int mt = 0; mt < MT; mt++) {
        float sl = 0.f, dl = 0.f, sh = 0.f, dh = 0.f;
#pragma unroll
        for (int nt = 0; nt < NT; nt++) {
            sl += acc[mt][nt][0] * aS0[nt] + acc[mt][nt][1] * aS1[nt];
            dl += acc[mt][nt][0] * aD0[nt] + acc[mt][nt][1] * aD1[nt];
            sh += acc[mt][nt][2] * aS0[nt] + acc[mt][nt][3] * aS1[nt];
            dh += acc[mt][nt][2] * aD0[nt] + acc[mt][nt][3] * aD1[nt];
        }
        sl += __shfl_down_sync(FULL, sl, 2); sl += __shfl_down_sync(FULL, sl, 1);
        dl += __shfl_down_sync(FULL, dl, 2); dl += __shfl_down_sync(FULL, dl, 1);
        sh += __shfl_down_sync(FULL, sh, 2); sh += __shfl_down_sync(FULL, sh, 1);
        dh += __shfl_down_sync(FULL, dh, 2); dh += __shfl_down_sync(FULL, dh, 1);
        if (tg == 0) {
            int lr = wm * 64 + mt * 16 + g;
            atomicAdd(&s_as[lr][lh], sl);
            atomicAdd(&s_ad[lr][lh], dl);
            atomicAdd(&s_as[lr + 8][lh], sh);
            atomicAdd(&s_ad[lr + 8][lh], dh);
        }
    }
    __syncthreads();

    int HS = Ncol >> 6;
    int hb = colBase >> 6;
    for (int i = tid; i < BM * LH; i += 256) {
        int r = i / LH, h = i % LH;
        int gr = rowBase + r;
        if (gr < M) {
            as_out[gr * HS + hb + h] = s_as[r][h];
            ad_out[gr * HS + hb + h] = s_ad[r][h];
        }
    }
}

// ---------------- layer-1 aggregation: warp per (node, head), no barriers ----------------
__global__ __launch_bounds__(256)
void agg1_kernel(const float* __restrict__ bias) {
    int gw = blockIdx.x * 8 + (threadIdx.x >> 5);
    int lane = threadIdx.x & 31;
    if (gw >= NN * HH) return;
    int n = gw >> 2;
    int h = gw & 3;

    int beg = g_off[n];
    int deg = g_off[n + 1] - beg;
    float adh = g_ad1[n * 4 + h];

    const __nv_bfloat162* __restrict__ hb =
        (const __nv_bfloat162*)(g_h1b) + (size_t)h * 32 + lane;  // + src*128 later

    float2 acc = make_float2(0.f, 0.f);
    float dpart = 0.f;

    for (int ch = 0; ch < deg; ch += 32) {
        int m = min(32, deg - ch);
        int src = 0;
        float w = 0.f;
        if (lane < m) {
            src = g_srcs[beg + ch + lane];
            w = __expf(lrelu(g_as1[src * 4 + h] + adh));
        }
        dpart += w;
        int j = 0;
        for (; j + 2 <= m; j += 2) {
            int s0 = __shfl_sync(FULL, src, j);
            float w0 = __shfl_sync(FULL, w, j);
            int s1 = __shfl_sync(FULL, src, j + 1);
            float w1 = __shfl_sync(FULL, w, j + 1);
            float2 f0 = __bfloat1622float2(hb[(size_t)s0 * 128]);
            float2 f1 = __bfloat1622float2(hb[(size_t)s1 * 128]);
            acc.x = fmaf(f0.x, w0, acc.x);
            acc.y = fmaf(f0.y, w0, acc.y);
            acc.x = fmaf(f1.x, w1, acc.x);
            acc.y = fmaf(f1.y, w1, acc.y);
        }
        for (; j < m; j++) {
            int s0 = __shfl_sync(FULL, src, j);
            float w0 = __shfl_sync(FULL, w, j);
            float2 f0 = __bfloat1622float2(hb[(size_t)s0 * 128]);
            acc.x = fmaf(f0.x, w0, acc.x);
            acc.y = fmaf(f0.y, w0, acc.y);
        }
    }

    float rd = 1.f / (warpXorSum(dpart) + 1e-16f);
    int c = h * CC + lane * 2;
    float vx = acc.x * rd + bias[c];
    float vy = acc.y * rd + bias[c + 1];
    *(float2*)(g_x1 + (size_t)n * F1 + c) = make_float2(fmaxf(vx, 0.f), fmaxf(vy, 0.f));
}

// ---------------- layer-2 aggregation: warp per node + log_softmax ----------------
__global__ __launch_bounds__(256)
void agg2_kernel(const float* __restrict__ bias, float* __restrict__ out) {
    int n = blockIdx.x * 8 + (threadIdx.x >> 5);
    int lane = threadIdx.x & 31;
    if (n >= NN) return;

    int beg = g_off[n];
    int deg = g_off[n + 1] - beg;
    float ad = g_ad2[n];

    const __nv_bfloat162* __restrict__ hb =
        (const __nv_bfloat162*)(g_h2b) + lane;  // + src*32 later

    float2 acc = make_float2(0.f, 0.f);
    float dpart = 0.f;

    for (int ch = 0; ch < deg; ch += 32) {
        int m = min(32, deg - ch);
        int src = 0;
        float w = 0.f;
        if (lane < m) {
            src = g_srcs[beg + ch + lane];
            w = __expf(lrelu(g_as2[src] + ad));
        }
        dpart += w;
        int j = 0;
        for (; j + 2 <= m; j += 2) {
            int s0 = __shfl_sync(FULL, src, j);
            float w0 = __shfl_sync(FULL, w, j);
            int s1 = __shfl_sync(FULL, src, j + 1);
            float w1 = __shfl_sync(FULL, w, j + 1);
            float2 f0 = __bfloat1622float2(hb[(size_t)s0 * 32]);
            float2 f1 = __bfloat1622float2(hb[(size_t)s1 * 32]);
            acc.x = fmaf(f0.x, w0, acc.x);
            acc.y = fmaf(f0.y, w0, acc.y);
            acc.x = fmaf(f1.x, w1, acc.x);
            acc.y = fmaf(f1.y, w1, acc.y);
        }
        for (; j < m; j++) {
            int s0 = __shfl_sync(FULL, src, j);
            float w0 = __shfl_sync(FULL, w, j);
            float2 f0 = __bfloat1622float2(hb[(size_t)s0 * 32]);
            acc.x = fmaf(f0.x, w0, acc.x);
            acc.y = fmaf(f0.y, w0, acc.y);
        }
    }

    float rd = 1.f / (warpXorSum(dpart) + 1e-16f);
    float vx = acc.x * rd + bias[lane * 2];
    float vy = acc.y * rd + bias[lane * 2 + 1];

    // log_softmax over the 64 values (2 per lane)
    float MM = warpXorMax(fmaxf(vx, vy));
    float S = warpXorSum(__expf(vx - MM) + __expf(vy - MM));
    float ls = logf(S);
    *(float2*)(out + (size_t)n * OC + lane * 2) =
        make_float2(vx - MM - ls, vy - MM - ls);
}

// ---------------- launch ----------------
static cudaStream_t s_side = 0;
static cudaEvent_t  s_evFork = 0, s_evJoin = 0;

extern "C" void kernel_launch(void* const* d_in, const int* in_sizes, int n_in,
                              void* d_out, int out_size) {
    const float* x        = (const float*)d_in[0];
    const void*  ei       = d_in[1];
    const float* W1       = (const float*)d_in[2];
    const float* att_src1 = (const float*)d_in[3];
    const float* att_dst1 = (const float*)d_in[4];
    const float* b1       = (const float*)d_in[5];
    const float* W2       = (const float*)d_in[6];
    const float* att_src2 = (const float*)d_in[7];
    const float* att_dst2 = (const float*)d_in[8];
    const float* b2       = (const float*)d_in[9];
    float* out            = (float*)d_out;

    if (!s_side) {
        cudaStreamCreateWithFlags(&s_side, cudaStreamNonBlocking);
        cudaEventCreateWithFlags(&s_evFork, cudaEventDisableTiming);
        cudaEventCreateWithFlags(&s_evJoin, cudaEventDisableTiming);
    }

    void *p_h1b, *p_x1, *p_h2b, *p_as1, *p_ad1, *p_as2, *p_ad2;
    cudaGetSymbolAddress(&p_h1b, g_h1b);
    cudaGetSymbolAddress(&p_x1, g_x1);
    cudaGetSymbolAddress(&p_h2b, g_h2b);
    cudaGetSymbolAddress(&p_as1, g_as1);
    cudaGetSymbolAddress(&p_ad1, g_ad1);
    cudaGetSymbolAddress(&p_as2, g_as2);
    cudaGetSymbolAddress(&p_ad2, g_ad2);

    // fork: CSR build on side stream, concurrent with GEMM1 on main
    cudaEventRecord(s_evFork, 0);
    cudaStreamWaitEvent(s_side, s_evFork, 0);

    detect_kernel<<<1, 32, 0, s_side>>>(ei);
    zero_deg_kernel<<<NB, 256, 0, s_side>>>();
    count_kernel<<<(ET + 255) / 256, 256, 0, s_side>>>(ei);
    scan_partial_kernel<<<NB, 256, 0, s_side>>>();
    scan_top_kernel<<<1, 256, 0, s_side>>>();
    scan_write_kernel<<<NB, 256, 0, s_side>>>();
    fill_kernel<<<(ET + 255) / 256, 256, 0, s_side>>>(ei);
    cudaEventRecord(s_evJoin, s_side);

    // main stream: layer-1 GEMM (+ fused att dots, bf16 out)
    gemm_att_kernel<128>
        <<<dim3(F1 / 128, (NN + 127) / 128), 256>>>(
            x, W1, (__nv_bfloat16*)p_h1b, att_src1, att_dst1,
            (float*)p_as1, (float*)p_ad1, NN, F1, 256);

    // join: agg1 needs CSR + GEMM1
    cudaStreamWaitEvent(0, s_evJoin, 0);
    agg1_kernel<<<(NN * HH + 7) / 8, 256>>>(b1);

    // layer 2
    gemm_att_kernel<64>
        <<<dim3(1, (NN + 127) / 128), 256>>>(
            (const float*)p_x1, W2, (__nv_bfloat16*)p_h2b, att_src2, att_dst2,
            (float*)p_as2, (float*)p_ad2, NN, OC, F1);
    agg2_kernel<<<(NN + 7) / 8, 256>>>(b2, out);
}

// round 9
// speedup vs baseline: 3.5681x; 1.2413x over previous
#include <cuda_runtime.h>
#include <cuda_bf16.h>
#include <math.h>
#include <stdint.h>

// Problem constants
#define NN 50000
#define EE 800000
#define ET 850000   // EE + NN self loops
#define F1 256      // HEADS*HID
#define HH 4
#define CC 64
#define OC 64
#define NB 196      // ceil(NN/256)

#define FULL 0xffffffffu

// ---------------- device scratch ----------------
__device__ __nv_bfloat16 g_h1b[(size_t)NN * F1];  // x @ W1 (bf16)
__device__ __nv_bfloat16 g_x1b[(size_t)NN * F1];  // layer-1 output (bf16)
__device__ __nv_bfloat16 g_h2b[(size_t)NN * OC];  // x1 @ W2 (bf16)
__device__ float  g_as1[NN * HH];
__device__ float  g_ad1[NN * HH];
__device__ float  g_as2[NN];
__device__ float  g_ad2[NN];
__device__ int    g_deg[NB * 256];
__device__ int    g_off[NN + 1];
__device__ int    g_pos[NN];
__device__ int    g_srcs[ET];
__device__ int    g_bsum[256];
__device__ int    g_boff[256];
__device__ int    g_is64;

// ---------------- helpers ----------------
__device__ __forceinline__ float warpXorSum(float v) {
#pragma unroll
    for (int o = 16; o; o >>= 1) v += __shfl_xor_sync(FULL, v, o);
    return v;
}
__device__ __forceinline__ float warpXorMax(float v) {
#pragma unroll
    for (int o = 16; o; o >>= 1) v = fmaxf(v, __shfl_xor_sync(FULL, v, o));
    return v;
}
__device__ __forceinline__ float lrelu(float x) { return x > 0.f ? x : 0.2f * x; }

__device__ __forceinline__ int load_edge(const void* eiv, int idx) {
    if (g_is64) return (int)((const long long*)eiv)[idx];
    return ((const int*)eiv)[idx];
}

__device__ __forceinline__ uint32_t f2tf32(float f) {
    uint32_t u;
    asm("cvt.rna.tf32.f32 %0, %1;" : "=r"(u) : "f"(f));
    return u;
}

__device__ __forceinline__ void mma_tf32(float c[4],
                                         uint32_t a0, uint32_t a1, uint32_t a2, uint32_t a3,
                                         uint32_t b0, uint32_t b1) {
    asm volatile(
        "mma.sync.aligned.m16n8k8.row.col.f32.tf32.tf32.f32 "
        "{%0,%1,%2,%3},{%4,%5,%6,%7},{%8,%9},{%0,%1,%2,%3};"
        : "+f"(c[0]), "+f"(c[1]), "+f"(c[2]), "+f"(c[3])
        : "r"(a0), "r"(a1), "r"(a2), "r"(a3), "r"(b0), "r"(b1));
}

// ---------------- dtype sniff ----------------
__global__ void detect_kernel(const void* eiv) {
    if (threadIdx.x == 0) {
        const long long* p = (const long long*)eiv;
        int ok = 1;
        for (int i = 0; i < 256; i++) {
            long long v = p[i];
            if (v < 0 || v >= NN) { ok = 0; break; }
        }
        g_is64 = ok;
    }
}

// ---------------- CSR build ----------------
__global__ void zero_deg_kernel() {
    int i = blockIdx.x * blockDim.x + threadIdx.x;
    if (i < NB * 256) g_deg[i] = 0;
}

__global__ void count_kernel(const void* __restrict__ eiv) {
    int e = blockIdx.x * blockDim.x + threadIdx.x;
    if (e >= ET) return;
    int dst = (e < EE) ? load_edge(eiv, EE + e) : (e - EE);
    atomicAdd(&g_deg[dst], 1);
}

__global__ void scan_partial_kernel() {
    int tid = threadIdx.x;
    int lane = tid & 31, wid = tid >> 5;
    int v = g_deg[blockIdx.x * 256 + tid];
    int s = v;
#pragma unroll
    for (int o = 16; o; o >>= 1) s += __shfl_down_sync(FULL, s, o);
    __shared__ int ws[8];
    if (lane == 0) ws[wid] = s;
    __syncthreads();
    if (tid == 0) {
        int t = 0;
#pragma unroll
        for (int w = 0; w < 8; w++) t += ws[w];
        g_bsum[blockIdx.x] = t;
    }
}

__global__ void scan_top_kernel() {
    int tid = threadIdx.x;
    int lane = tid & 31, wid = tid >> 5;
    int d = (tid < NB) ? g_bsum[tid] : 0;
    int v = d;
#pragma unroll
    for (int o = 1; o < 32; o <<= 1) {
        int u = __shfl_up_sync(FULL, v, o);
        if (lane >= o) v += u;
    }
    __shared__ int ws[8];
    if (lane == 31) ws[wid] = v;
    __syncthreads();
    __shared__ int wo[8];
    if (tid == 0) {
        int r = 0;
#pragma unroll
        for (int w = 0; w < 8; w++) { wo[w] = r; r += ws[w]; }
    }
    __syncthreads();
    if (tid < NB) g_boff[tid] = v - d + wo[wid];
}

__global__ void scan_write_kernel() {
    int tid = threadIdx.x;
    int lane = tid & 31, wid = tid >> 5;
    int i = blockIdx.x * 256 + tid;
    int d = g_deg[i];
    int v = d;
#pragma unroll
    for (int o = 1; o < 32; o <<= 1) {
        int u = __shfl_up_sync(FULL, v, o);
        if (lane >= o) v += u;
    }
    __shared__ int ws[8];
    if (lane == 31) ws[wid] = v;
    __syncthreads();
    __shared__ int wo[8];
    if (tid == 0) {
        int r = 0;
#pragma unroll
        for (int w = 0; w < 8; w++) { wo[w] = r; r += ws[w]; }
    }
    __syncthreads();
    int excl = v - d + wo[wid] + g_boff[blockIdx.x];
    if (i < NN) {
        g_off[i] = excl;
        g_pos[i] = excl;
        if (i == NN - 1) g_off[NN] = excl + d;
    }
}

__global__ void fill_kernel(const void* __restrict__ eiv) {
    int e = blockIdx.x * blockDim.x + threadIdx.x;
    if (e >= ET) return;
    int src, dst;
    if (e < EE) { src = load_edge(eiv, e); dst = load_edge(eiv, EE + e); }
    else        { src = dst = e - EE; }
    int p = atomicAdd(&g_pos[dst], 1);
    g_srcs[p] = src;
}

// ---------------- TF32 GEMM + fused attention dots + bf16 output ----------------
// A: MxK row-major (fp32 or bf16, template AT), B: KxN fp32 row-major.
// Cb: MxN bf16.  as_out/ad_out: per-row per-head dot(att, row).
template <int BN, typename AT>
__global__ __launch_bounds__(256)
void gemm_att_kernel(const AT* __restrict__ A, const float* __restrict__ B,
                     __nv_bfloat16* __restrict__ Cb,
                     const float* __restrict__ atts, const float* __restrict__ attd,
                     float* __restrict__ as_out, float* __restrict__ ad_out,
                     int M, int Ncol, int K) {
    constexpr int BM = 128;
    constexpr int BK = 32;
    constexpr int PAD = 4;
    constexpr int WN = BN / 4;
    constexpr int MT = 4;
    constexpr int NT = WN / 8;
    constexpr int LH = BN / 64;
    constexpr bool ABF = (sizeof(AT) == 2);
    constexpr int EPL = ABF ? 8 : 4;                   // A elems per 16B load
    constexpr int A_LD = (BM * BK) / (256 * EPL);
    constexpr int ACH = BK / EPL;                      // 16B chunks per A row
    constexpr int B_LD = (BK * BN) / (256 * 4);
    constexpr int BB4 = BN / 4;

    __shared__ uint32_t As[BM][BK + PAD];
    __shared__ uint32_t Bs[BK][BN + PAD];
    __shared__ float s_as[BM][LH];
    __shared__ float s_ad[BM][LH];

    const int tid = threadIdx.x;
    const int lane = tid & 31, wid = tid >> 5;
    const int wm = wid & 1, wn = wid >> 1;
    const int g = lane >> 2, tg = lane & 3;
    const int rowBase = blockIdx.y * BM;
    const int colBase = blockIdx.x * BN;
    const int lh = (wn * WN) >> 6;

    float acc[MT][NT][4];
#pragma unroll
    for (int i = 0; i < MT; i++)
#pragma unroll
        for (int j = 0; j < NT; j++)
#pragma unroll
            for (int t = 0; t < 4; t++) acc[i][j][t] = 0.f;

    uint4 ra[A_LD];
    float4 rb[B_LD];

#pragma unroll
    for (int t = 0; t < A_LD; t++) {
        int idx = t * 256 + tid;
        int r = idx / ACH, c = idx % ACH;
        int row = rowBase + r;
        ra[t] = (row < M) ? *(const uint4*)(A + (size_t)row * K + c * EPL)
                          : make_uint4(0u, 0u, 0u, 0u);
    }
#pragma unroll
    for (int t = 0; t < B_LD; t++) {
        int idx = t * 256 + tid;
        int r = idx / BB4, c = idx % BB4;
        rb[t] = *(const float4*)(B + (size_t)r * Ncol + colBase + c * 4);
    }

    for (int k0 = 0; k0 < K; k0 += BK) {
#pragma unroll
        for (int t = 0; t < A_LD; t++) {
            int idx = t * 256 + tid;
            int r = idx / ACH, c = idx % ACH;
            if (ABF) {
                const uint32_t* p = (const uint32_t*)&ra[t];
#pragma unroll
                for (int q = 0; q < 4; q++) {
                    float2 f = __bfloat1622float2(*(const __nv_bfloat162*)&p[q]);
                    As[r][c * 8 + q * 2 + 0] = f2tf32(f.x);
                    As[r][c * 8 + q * 2 + 1] = f2tf32(f.y);
                }
            } else {
                As[r][c * 4 + 0] = f2tf32(__uint_as_float(ra[t].x));
                As[r][c * 4 + 1] = f2tf32(__uint_as_float(ra[t].y));
                As[r][c * 4 + 2] = f2tf32(__uint_as_float(ra[t].z));
                As[r][c * 4 + 3] = f2tf32(__uint_as_float(ra[t].w));
            }
        }
#pragma unroll
        for (int t = 0; t < B_LD; t++) {
            int idx = t * 256 + tid;
            int r = idx / BB4, c = idx % BB4;
            Bs[r][c * 4 + 0] = f2tf32(rb[t].x);
            Bs[r][c * 4 + 1] = f2tf32(rb[t].y);
            Bs[r][c * 4 + 2] = f2tf32(rb[t].z);
            Bs[r][c * 4 + 3] = f2tf32(rb[t].w);
        }
        __syncthreads();

        int kn = k0 + BK;
        if (kn < K) {
#pragma unroll
            for (int t = 0; t < A_LD; t++) {
                int idx = t * 256 + tid;
                int r = idx / ACH, c = idx % ACH;
                int row = rowBase + r;
                ra[t] = (row < M) ? *(const uint4*)(A + (size_t)row * K + kn + c * EPL)
                                  : make_uint4(0u, 0u, 0u, 0u);
            }
#pragma unroll
            for (int t = 0; t < B_LD; t++) {
                int idx = t * 256 + tid;
                int r = idx / BB4, c = idx % BB4;
                rb[t] = *(const float4*)(B + (size_t)(kn + r) * Ncol + colBase + c * 4);
            }
        }

#pragma unroll
        for (int ks = 0; ks < 4; ks++) {
            int kb = ks * 8;
            uint32_t af[MT][4];
#pragma unroll
            for (int mt = 0; mt < MT; mt++) {
                int r0 = wm * 64 + mt * 16 + g;
                af[mt][0] = As[r0][kb + tg];
                af[mt][1] = As[r0 + 8][kb + tg];
                af[mt][2] = As[r0][kb + tg + 4];
                af[mt][3] = As[r0 + 8][kb + tg + 4];
            }
            uint32_t bf[NT][2];
#pragma unroll
            for (int nt = 0; nt < NT; nt++) {
                int n = wn * WN + nt * 8 + g;
                bf[nt][0] = Bs[kb + tg][n];
                bf[nt][1] = Bs[kb + tg + 4][n];
            }
#pragma unroll
            for (int mt = 0; mt < MT; mt++)
#pragma unroll
                for (int nt = 0; nt < NT; nt++)
                    mma_tf32(acc[mt][nt], af[mt][0], af[mt][1], af[mt][2], af[mt][3],
                             bf[nt][0], bf[nt][1]);
        }
        __syncthreads();
    }

    // ---- epilogue: bf16 store ----
#pragma unroll
    for (int mt = 0; mt < MT; mt++) {
#pragma unroll
        for (int nt = 0; nt < NT; nt++) {
            int row = rowBase + wm * 64 + mt * 16 + g;
            int col = colBase + wn * WN + nt * 8 + tg * 2;
            if (row < M)
                *(__nv_bfloat162*)(Cb + (size_t)row * Ncol + col) =
                    __float22bfloat162_rn(make_float2(acc[mt][nt][0], acc[mt][nt][1]));
            if (row + 8 < M)
                *(__nv_bfloat162*)(Cb + (size_t)(row + 8) * Ncol + col) =
                    __float22bfloat162_rn(make_float2(acc[mt][nt][2], acc[mt][nt][3]));
        }
    }

    // ---- epilogue: attention dots from exact fp32 accumulators ----
    for (int i = tid; i < BM * LH; i += 256) {
        ((float*)s_as)[i] = 0.f;
        ((float*)s_ad)[i] = 0.f;
    }
    __syncthreads();

    float aS0[NT], aS1[NT], aD0[NT], aD1[NT];
#pragma unroll
    for (int nt = 0; nt < NT; nt++) {
        int c = colBase + wn * WN + nt * 8 + tg * 2;
        aS0[nt] = atts[c];  aS1[nt] = atts[c + 1];
        aD0[nt] = attd[c];  aD1[nt] = attd[c + 1];
    }
#pragma unroll
    for (int mt = 0; mt < MT; mt++) {
        float sl = 0.f, dl = 0.f, sh = 0.f, dh = 0.f;
#pragma unroll
        for (int nt = 0; nt < NT; nt++) {
            sl += acc[mt][nt][0] * aS0[nt] + acc[mt][nt][1] * aS1[nt];
            dl += acc[mt][nt][0] * aD0[nt] + acc[mt][nt][1] * aD1[nt];
            sh += acc[mt][nt][2] * aS0[nt] + acc[mt][nt][3] * aS1[nt];
            dh += acc[mt][nt][2] * aD0[nt] + acc[mt][nt][3] * aD1[nt];
        }
        sl += __shfl_down_sync(FULL, sl, 2); sl += __shfl_down_sync(FULL, sl, 1);
        dl += __shfl_down_sync(FULL, dl, 2); dl += __shfl_down_sync(FULL, dl, 1);
        sh += __shfl_down_sync(FULL, sh, 2); sh += __shfl_down_sync(FULL, sh, 1);
        dh += __shfl_down_sync(FULL, dh, 2); dh += __shfl_down_sync(FULL, dh, 1);
        if (tg == 0) {
            int lr = wm * 64 + mt * 16 + g;
            atomicAdd(&s_as[lr][lh], sl);
            atomicAdd(&s_ad[lr][lh], dl);
            atomicAdd(&s_as[lr + 8][lh], sh);
            atomicAdd(&s_ad[lr + 8][lh], dh);
        }
    }
    __syncthreads();

    int HS = Ncol >> 6;
    int hb = colBase >> 6;
    for (int i = tid; i < BM * LH; i += 256) {
        int r = i / LH, h = i % LH;
        int gr = rowBase + r;
        if (gr < M) {
            as_out[gr * HS + hb + h] = s_as[r][h];
            ad_out[gr * HS + hb + h] = s_ad[r][h];
        }
    }
}

// ---------------- layer-1 aggregation: ONE warp per node, all 4 heads ----------------
// lane owns 8 channels (uint4 of bf16); per-edge 4-head weights exchanged via smem.
__global__ __launch_bounds__(256)
void agg1_kernel(const float* __restrict__ bias) {
    int n = blockIdx.x * 8 + (threadIdx.x >> 5);
    int lane = threadIdx.x & 31;
    int wb = threadIdx.x >> 5;
    __shared__ float s_w[8][32][4];
    if (n >= NN) return;

    int beg = g_off[n];
    int deg = g_off[n + 1] - beg;
    float4 ad = *(const float4*)&g_ad1[n * 4];
    int head = lane >> 3;          // channels [lane*8, lane*8+8) all in this head

    float2 a0 = make_float2(0.f, 0.f), a1 = make_float2(0.f, 0.f);
    float2 a2 = make_float2(0.f, 0.f), a3 = make_float2(0.f, 0.f);
    float4 dp = make_float4(0.f, 0.f, 0.f, 0.f);

    const uint4* __restrict__ hrow = (const uint4*)g_h1b + lane;  // + src*32

    for (int ch = 0; ch < deg; ch += 32) {
        int m = min(32, deg - ch);
        int src = 0;
        if (lane < m) {
            src = g_srcs[beg + ch + lane];
            float4 as = *(const float4*)&g_as1[src * 4];
            float4 w;
            w.x = __expf(lrelu(as.x + ad.x));
            w.y = __expf(lrelu(as.y + ad.y));
            w.z = __expf(lrelu(as.z + ad.z));
            w.w = __expf(lrelu(as.w + ad.w));
            dp.x += w.x; dp.y += w.y; dp.z += w.z; dp.w += w.w;
            *(float4*)&s_w[wb][lane][0] = w;
        }
        __syncwarp();
        for (int j = 0; j < m; j++) {
            int s0 = __shfl_sync(FULL, src, j);
            float wj = s_w[wb][j][head];
            uint4 v = hrow[(size_t)s0 * 32];
            float2 f0 = __bfloat1622float2(*(const __nv_bfloat162*)&v.x);
            float2 f1 = __bfloat1622float2(*(const __nv_bfloat162*)&v.y);
            float2 f2 = __bfloat1622float2(*(const __nv_bfloat162*)&v.z);
            float2 f3 = __bfloat1622float2(*(const __nv_bfloat162*)&v.w);
            a0.x = fmaf(f0.x, wj, a0.x); a0.y = fmaf(f0.y, wj, a0.y);
            a1.x = fmaf(f1.x, wj, a1.x); a1.y = fmaf(f1.y, wj, a1.y);
            a2.x = fmaf(f2.x, wj, a2.x); a2.y = fmaf(f2.y, wj, a2.y);
            a3.x = fmaf(f3.x, wj, a3.x); a3.y = fmaf(f3.y, wj, a3.y);
        }
        __syncwarp();
    }

    dp.x = warpXorSum(dp.x);
    dp.y = warpXorSum(dp.y);
    dp.z = warpXorSum(dp.z);
    dp.w = warpXorSum(dp.w);
    float denom = (head == 0) ? dp.x : (head == 1) ? dp.y : (head == 2) ? dp.z : dp.w;
    float rd = 1.f / (denom + 1e-16f);

    int c0 = lane * 8;
    const float4* bp = (const float4*)(bias + c0);
    float4 b0 = bp[0], b1 = bp[1];
    __nv_bfloat162 o[4];
    o[0] = __float22bfloat162_rn(make_float2(fmaxf(a0.x * rd + b0.x, 0.f),
                                             fmaxf(a0.y * rd + b0.y, 0.f)));
    o[1] = __float22bfloat162_rn(make_float2(fmaxf(a1.x * rd + b0.z, 0.f),
                                             fmaxf(a1.y * rd + b0.w, 0.f)));
    o[2] = __float22bfloat162_rn(make_float2(fmaxf(a2.x * rd + b1.x, 0.f),
                                             fmaxf(a2.y * rd + b1.y, 0.f)));
    o[3] = __float22bfloat162_rn(make_float2(fmaxf(a3.x * rd + b1.z, 0.f),
                                             fmaxf(a3.y * rd + b1.w, 0.f)));
    *((uint4*)(g_x1b + (size_t)n * F1 + c0)) = *(const uint4*)o;
}

// ---------------- layer-2 aggregation: warp per node + log_softmax ----------------
__global__ __launch_bounds__(256)
void agg2_kernel(const float* __restrict__ bias, float* __restrict__ out) {
    int n = blockIdx.x * 8 + (threadIdx.x >> 5);
    int lane = threadIdx.x & 31;
    if (n >= NN) return;

    int beg = g_off[n];
    int deg = g_off[n + 1] - beg;
    float ad = g_ad2[n];

    const __nv_bfloat162* __restrict__ hb =
        (const __nv_bfloat162*)(g_h2b) + lane;  // + src*32

    float2 acc = make_float2(0.f, 0.f);
    float dpart = 0.f;

    for (int ch = 0; ch < deg; ch += 32) {
        int m = min(32, deg - ch);
        int src = 0;
        float w = 0.f;
        if (lane < m) {
            src = g_srcs[beg + ch + lane];
            w = __expf(lrelu(g_as2[src] + ad));
        }
        dpart += w;
        int j = 0;
        for (; j + 2 <= m; j += 2) {
            int s0 = __shfl_sync(FULL, src, j);
            float w0 = __shfl_sync(FULL, w, j);
            int s1 = __shfl_sync(FULL, src, j + 1);
            float w1 = __shfl_sync(FULL, w, j + 1);
            float2 f0 = __bfloat1622float2(hb[(size_t)s0 * 32]);
            float2 f1 = __bfloat1622float2(hb[(size_t)s1 * 32]);
            acc.x = fmaf(f0.x, w0, acc.x);
            acc.y = fmaf(f0.y, w0, acc.y);
            acc.x = fmaf(f1.x, w1, acc.x);
            acc.y = fmaf(f1.y, w1, acc.y);
        }
        for (; j < m; j++) {
            int s0 = __shfl_sync(FULL, src, j);
            float w0 = __shfl_sync(FULL, w, j);
            float2 f0 = __bfloat1622float2(hb[(size_t)s0 * 32]);
            acc.x = fmaf(f0.x, w0, acc.x);
            acc.y = fmaf(f0.y, w0, acc.y);
        }
    }

    float rd = 1.f / (warpXorSum(dpart) + 1e-16f);
    float vx = acc.x * rd + bias[lane * 2];
    float vy = acc.y * rd + bias[lane * 2 + 1];

    float MM = warpXorMax(fmaxf(vx, vy));
    float S = warpXorSum(__expf(vx - MM) + __expf(vy - MM));
    float ls = logf(S);
    *(float2*)(out + (size_t)n * OC + lane * 2) =
        make_float2(vx - MM - ls, vy - MM - ls);
}

// ---------------- launch ----------------
static cudaStream_t s_side = 0;
static cudaEvent_t  s_evFork = 0, s_evJoin = 0;

extern "C" void kernel_launch(void* const* d_in, const int* in_sizes, int n_in,
                              void* d_out, int out_size) {
    const float* x        = (const float*)d_in[0];
    const void*  ei       = d_in[1];
    const float* W1       = (const float*)d_in[2];
    const float* att_src1 = (const float*)d_in[3];
    const float* att_dst1 = (const float*)d_in[4];
    const float* b1       = (const float*)d_in[5];
    const float* W2       = (const float*)d_in[6];
    const float* att_src2 = (const float*)d_in[7];
    const float* att_dst2 = (const float*)d_in[8];
    const float* b2       = (const float*)d_in[9];
    float* out            = (float*)d_out;

    if (!s_side) {
        cudaStreamCreateWithFlags(&s_side, cudaStreamNonBlocking);
        cudaEventCreateWithFlags(&s_evFork, cudaEventDisableTiming);
        cudaEventCreateWithFlags(&s_evJoin, cudaEventDisableTiming);
    }

    void *p_h1b, *p_x1b, *p_h2b, *p_as1, *p_ad1, *p_as2, *p_ad2;
    cudaGetSymbolAddress(&p_h1b, g_h1b);
    cudaGetSymbolAddress(&p_x1b, g_x1b);
    cudaGetSymbolAddress(&p_h2b, g_h2b);
    cudaGetSymbolAddress(&p_as1, g_as1);
    cudaGetSymbolAddress(&p_ad1, g_ad1);
    cudaGetSymbolAddress(&p_as2, g_as2);
    cudaGetSymbolAddress(&p_ad2, g_ad2);

    // fork: CSR build on side stream, concurrent with GEMM1 on main
    cudaEventRecord(s_evFork, 0);
    cudaStreamWaitEvent(s_side, s_evFork, 0);

    detect_kernel<<<1, 32, 0, s_side>>>(ei);
    zero_deg_kernel<<<NB, 256, 0, s_side>>>();
    count_kernel<<<(ET + 255) / 256, 256, 0, s_side>>>(ei);
    scan_partial_kernel<<<NB, 256, 0, s_side>>>();
    scan_top_kernel<<<1, 256, 0, s_side>>>();
    scan_write_kernel<<<NB, 256, 0, s_side>>>();
    fill_kernel<<<(ET + 255) / 256, 256, 0, s_side>>>(ei);
    cudaEventRecord(s_evJoin, s_side);

    // main stream: layer-1 GEMM (+ fused att dots, bf16 out)
    gemm_att_kernel<128, float>
        <<<dim3(F1 / 128, (NN + 127) / 128), 256>>>(
            x, W1, (__nv_bfloat16*)p_h1b, att_src1, att_dst1,
            (float*)p_as1, (float*)p_ad1, NN, F1, 256);

    // join: agg1 needs CSR + GEMM1
    cudaStreamWaitEvent(0, s_evJoin, 0);
    agg1_kernel<<<(NN + 7) / 8, 256>>>(b1);

    // layer 2 (A = bf16 x1)
    gemm_att_kernel<64, __nv_bfloat16>
        <<<dim3(1, (NN + 127) / 128), 256>>>(
            (const __nv_bfloat16*)p_x1b, W2, (__nv_bfloat16*)p_h2b, att_src2, att_dst2,
            (float*)p_as2, (float*)p_ad2, NN, OC, F1);
    agg2_kernel<<<(NN + 7) / 8, 256>>>(b2, out);
}